// round 2
// baseline (speedup 1.0000x reference)
#include <cuda_runtime.h>
#include <cstdint>
#include <cstddef>

#define NN 100000
#define DD 128
#define AA 3
#define PP 50000
#define EE 500000
#define EFN 500000

#define ND  ((size_t)NN * DD)
#define AND ((size_t)AA * NN * DD)
#define PD  ((size_t)PP * DD)

typedef unsigned long long ull;

// ---------------- scratch (static device globals; no allocation) ----------------
__device__ float  g_xatt_a[AA * NN * DD];
__device__ float  g_xatt_b[AA * NN * DD];
__device__ float  g_agg   [AA * NN * DD];
__device__ float  g_agg3  [NN * DD];
__device__ float  g_cnt   [AA * NN];
__device__ float  g_cnt3  [NN];
__device__ float  g_esf   [AA * PP * DD];
__device__ float  g_wt    [262144];          // transposed weights, [i][o] layout
__device__ double g_inv   [AA * 128 * 256];  // Gauss-Jordan scratch
__device__ float  g_M     [AA * 128 * 128];  // inv(proj)+I, [i][o]

#define WT_AGG1 0
#define WT_AGG2 16384
#define WT_L1   32768
#define WT_R1   81920
#define WT_L2   131072
#define WT_R2   180224
#define WT_L3   229376
#define WT_R3   245760

// packed f32x2 helpers (sm_100+): FFMA2 is only reachable via PTX
#define FFMA2(d, a, b) asm("fma.rn.f32x2 %0, %1, %2, %0;" : "+l"(d) : "l"(a), "l"(b))
#define PACKDUP(d, x)  do { unsigned _u = __float_as_uint(x); \
    asm("mov.b64 %0, {%1, %1};" : "=l"(d) : "r"(_u)); } while (0)

union F2U { ull u; float2 f; };

// ---------------- weight transpose: dst[b][i][o] = src[b*bstride + o*ld + i] ----
__global__ void transpose_wt(float* __restrict__ dst, const float* __restrict__ src,
                             int ldsrc, long bstride) {
    int b = blockIdx.x;
    const float* s = src + (size_t)b * bstride;
    float* d = dst + (size_t)b * 16384;
    for (int idx = threadIdx.x; idx < 16384; idx += blockDim.x) {
        int i = idx >> 7, o = idx & 127;
        d[idx] = s[(size_t)o * ldsrc + i];
    }
}

// ---------------- fp64 Gauss-Jordan with partial pivoting; M = inv(proj)+I -----
__global__ void inv_kernel(const float* __restrict__ proj) {
    int a = blockIdx.x;
    double* A = g_inv + (size_t)a * 128 * 256;
    int tid = threadIdx.x;  // 256 threads

    for (int idx = tid; idx < 128 * 256; idx += 256) {
        int r = idx >> 8, c = idx & 255;
        A[idx] = (c < 128) ? (double)proj[(size_t)a * 16384 + r * 128 + c]
                           : ((c - 128) == r ? 1.0 : 0.0);
    }
    __syncthreads();

    __shared__ double pv[128];
    __shared__ int    pi[128];
    for (int k = 0; k < 128; k++) {
        if (tid < 128) {
            pv[tid] = (tid >= k) ? fabs(A[(size_t)tid * 256 + k]) : -1.0;
            pi[tid] = tid;
        }
        __syncthreads();
        for (int s = 64; s > 0; s >>= 1) {
            if (tid < s && pv[tid + s] > pv[tid]) { pv[tid] = pv[tid + s]; pi[tid] = pi[tid + s]; }
            __syncthreads();
        }
        int piv = pi[0];
        if (piv != k && tid < 256) {
            double t = A[(size_t)k * 256 + tid];
            A[(size_t)k * 256 + tid] = A[(size_t)piv * 256 + tid];
            A[(size_t)piv * 256 + tid] = t;
        }
        __syncthreads();
        double pinv = 1.0 / A[(size_t)k * 256 + k];
        A[(size_t)k * 256 + tid] *= pinv;
        __syncthreads();
        int r = tid >> 1, h = tid & 1;
        double f = (r != k) ? A[(size_t)r * 256 + k] : 0.0;
        __syncthreads();
        if (r != k) {
            int j0 = h * 128;
            #pragma unroll 4
            for (int j = j0; j < j0 + 128; j++)
                A[(size_t)r * 256 + j] -= f * A[(size_t)k * 256 + j];
        }
        __syncthreads();
    }
    for (int idx = tid; idx < 16384; idx += 256) {
        int i = idx >> 7, o = idx & 127;
        g_M[(size_t)a * 16384 + idx] =
            (float)(A[(size_t)i * 256 + 128 + o] + (i == o ? 1.0 : 0.0));
    }
}

// ---------------- edge scatter: agg[si[e]] += data[gi[e]]; cnt[si[e]] += 1 ------
// 16B vector reduction (red.global.add.v4.f32, PTX ISA 8.3+/sm_90+): 1 REDG.128
// instead of 4 REDG.32 -> 4x fewer LTS atomic ops.
__global__ __launch_bounds__(256)
void scatter_add(const float* __restrict__ data,
                 const int* __restrict__ gi,
                 const int* __restrict__ si,
                 float* __restrict__ agg,
                 float* __restrict__ cnt, int ne) {
    int t = blockIdx.x * blockDim.x + threadIdx.x;
    int w = t >> 5, lane = t & 31;
    if (w >= ne) return;
    int g = gi[w], s = si[w];
    float4 v = ((const float4*)(data + (size_t)g * DD))[lane];
    float* dp = agg + (size_t)s * DD + lane * 4;
    asm volatile("red.global.add.v4.f32 [%0], {%1, %2, %3, %4};"
                 :: "l"(dp), "f"(v.x), "f"(v.y), "f"(v.z), "f"(v.w) : "memory");
    if (lane == 0) atomicAdd(cnt + s, 1.0f);
}

// ---------------- fused GEMM, packed-f32x2 math ---------------------------------
// Out[row] = act( scale(row)*In1[row] @ Wt1 + In2[row] @ Wt2 + bias )
// Wt layout: [i][o] (pre-transposed). Block = 128 rows x full 128 cols, BK=8.
// A stored so row-pairs pack directly into f32x2 operands; W stored duplicated
// (w,w) in smem so no per-k pack instructions are needed.
template<bool HAS2, bool GATHER, bool HASCNT, bool RELU, bool HASBIAS>
__global__ __launch_bounds__(256, 2)
void gemm128(const float* __restrict__ In1, int in1Stride,
             const float* __restrict__ Wt1,
             const float* __restrict__ In2,
             const float* __restrict__ Wt2,
             const float* __restrict__ bias,
             const float* __restrict__ cnt,
             const int*   __restrict__ ridx,
             float* __restrict__ Out,
             int nrows) {
    __shared__ __align__(16) float sA1[8][132];
    __shared__ __align__(16) float sA2[8][132];
    __shared__ __align__(16) ull   sW1d[8][128];   // duplicated (w,w) pairs
    __shared__ __align__(16) ull   sW2d[8][128];
    __shared__ int   sRow[128];
    __shared__ float sScale[128];

    int tid = threadIdx.x;
    int row0 = blockIdx.x * 128;

    if (tid < 128) {
        int g = row0 + tid;
        int e = 0; float sc = 0.0f;
        if (g < nrows) {
            e = GATHER ? ridx[g] : g;
            sc = 1.0f;
            if (HASCNT) sc = 1.0f / fmaxf(cnt[e], 1.0f);
        }
        sRow[tid] = e;
        sScale[tid] = sc;
    }
    __syncthreads();

    ull acc[4][8];
    #pragma unroll
    for (int r = 0; r < 4; r++)
        #pragma unroll
        for (int c = 0; c < 8; c++) acc[r][c] = 0ull;

    int tx = tid & 15, ty = tid >> 4;

    // fill-role indices
    int arow = tid >> 1, acs = tid & 1;   // A: 128 rows x 2 float4 per 8-float slice
    int wr = tid >> 5,  wc = tid & 31;    // W: 8 k-rows x 32 float4

    float a1s = sScale[arow];
    const float* a1p = In1 + (size_t)sRow[arow] * in1Stride + acs * 4;
    const float* a2p = nullptr;
    if (HAS2) {
        int g2 = row0 + arow; if (g2 >= nrows) g2 = 0;
        a2p = In2 + (size_t)g2 * DD + acs * 4;
    }
    const float* w1p = Wt1 + (size_t)wr * 128 + wc * 4;
    const float* w2p = HAS2 ? (Wt2 + (size_t)wr * 128 + wc * 4) : nullptr;

    for (int kt = 0; kt < 16; kt++) {
        int k0 = kt * 8;
        // ---- fill A (scaled) ----
        {
            float4 v = *(const float4*)(a1p + k0);
            sA1[acs * 4 + 0][arow] = v.x * a1s;
            sA1[acs * 4 + 1][arow] = v.y * a1s;
            sA1[acs * 4 + 2][arow] = v.z * a1s;
            sA1[acs * 4 + 3][arow] = v.w * a1s;
            if (HAS2) {
                float4 u = *(const float4*)(a2p + k0);
                sA2[acs * 4 + 0][arow] = u.x;
                sA2[acs * 4 + 1][arow] = u.y;
                sA2[acs * 4 + 2][arow] = u.z;
                sA2[acs * 4 + 3][arow] = u.w;
            }
        }
        // ---- fill W duplicated ----
        {
            float4 w = *(const float4*)(w1p + (size_t)k0 * 128);
            ull d0, d1, d2, d3;
            PACKDUP(d0, w.x); PACKDUP(d1, w.y); PACKDUP(d2, w.z); PACKDUP(d3, w.w);
            ulonglong2 pA; pA.x = d0; pA.y = d1;
            ulonglong2 pB; pB.x = d2; pB.y = d3;
            *(ulonglong2*)&sW1d[wr][wc * 4]     = pA;
            *(ulonglong2*)&sW1d[wr][wc * 4 + 2] = pB;
            if (HAS2) {
                float4 w2 = *(const float4*)(w2p + (size_t)k0 * 128);
                PACKDUP(d0, w2.x); PACKDUP(d1, w2.y); PACKDUP(d2, w2.z); PACKDUP(d3, w2.w);
                ulonglong2 qA; qA.x = d0; qA.y = d1;
                ulonglong2 qB; qB.x = d2; qB.y = d3;
                *(ulonglong2*)&sW2d[wr][wc * 4]     = qA;
                *(ulonglong2*)&sW2d[wr][wc * 4 + 2] = qB;
            }
        }
        __syncthreads();

        #pragma unroll
        for (int k = 0; k < 8; k++) {
            // A row pairs: packed directly from smem
            ulonglong2 ia = *(const ulonglong2*)&sA1[k][ty * 8];
            ulonglong2 ib = *(const ulonglong2*)&sA1[k][ty * 8 + 4];
            ull ivp0 = ia.x, ivp1 = ia.y, ivp2 = ib.x, ivp3 = ib.y;
            // W duplicated pairs
            ulonglong2 w0 = *(const ulonglong2*)&sW1d[k][tx * 8];
            ulonglong2 w1 = *(const ulonglong2*)&sW1d[k][tx * 8 + 2];
            ulonglong2 w2 = *(const ulonglong2*)&sW1d[k][tx * 8 + 4];
            ulonglong2 w3 = *(const ulonglong2*)&sW1d[k][tx * 8 + 6];
            ull wv[8] = {w0.x, w0.y, w1.x, w1.y, w2.x, w2.y, w3.x, w3.y};
            #pragma unroll
            for (int c = 0; c < 8; c++) {
                FFMA2(acc[0][c], ivp0, wv[c]);
                FFMA2(acc[1][c], ivp1, wv[c]);
                FFMA2(acc[2][c], ivp2, wv[c]);
                FFMA2(acc[3][c], ivp3, wv[c]);
            }
            if (HAS2) {
                ulonglong2 ja = *(const ulonglong2*)&sA2[k][ty * 8];
                ulonglong2 jb = *(const ulonglong2*)&sA2[k][ty * 8 + 4];
                ull jv0 = ja.x, jv1 = ja.y, jv2 = jb.x, jv3 = jb.y;
                ulonglong2 u0 = *(const ulonglong2*)&sW2d[k][tx * 8];
                ulonglong2 u1 = *(const ulonglong2*)&sW2d[k][tx * 8 + 2];
                ulonglong2 u2 = *(const ulonglong2*)&sW2d[k][tx * 8 + 4];
                ulonglong2 u3 = *(const ulonglong2*)&sW2d[k][tx * 8 + 6];
                ull uv[8] = {u0.x, u0.y, u1.x, u1.y, u2.x, u2.y, u3.x, u3.y};
                #pragma unroll
                for (int c = 0; c < 8; c++) {
                    FFMA2(acc[0][c], jv0, uv[c]);
                    FFMA2(acc[1][c], jv1, uv[c]);
                    FFMA2(acc[2][c], jv2, uv[c]);
                    FFMA2(acc[3][c], jv3, uv[c]);
                }
            }
        }
        __syncthreads();
    }

    float bv[8];
    #pragma unroll
    for (int c = 0; c < 8; c++) bv[c] = HASBIAS ? bias[tx * 8 + c] : 0.0f;

    #pragma unroll
    for (int r2 = 0; r2 < 4; r2++) {
        #pragma unroll
        for (int h = 0; h < 2; h++) {
            int lr = ty * 8 + r2 * 2 + h;
            int g = row0 + lr;
            if (g < nrows) {
                int orow = GATHER ? sRow[lr] : g;
                float* op = Out + (size_t)orow * DD + tx * 8;
                float v[8];
                #pragma unroll
                for (int c = 0; c < 8; c++) {
                    F2U u; u.u = acc[r2][c];
                    float x = (h ? u.f.y : u.f.x) + bv[c];
                    if (RELU) x = fmaxf(x, 0.0f);
                    v[c] = x;
                }
                *(float4*)op       = make_float4(v[0], v[1], v[2], v[3]);
                *((float4*)op + 1) = make_float4(v[4], v[5], v[6], v[7]);
            }
        }
    }
}

// ---------------- host orchestration -------------------------------------------
extern "C" void kernel_launch(void* const* d_in, const int* in_sizes, int n_in,
                              void* d_out, int out_size) {
    int iXI, iXA, iPF, iPOP, iEIA, iEIF, iPROJ, iAGGW, iAGGB,
        iWL1, iBL1, iWR1, iWL2, iBL2, iWR2, iWL3, iBL3, iWR3;
    if (in_sizes[3] == PP) {  // setup_inputs dict order
        iXI = 0; iXA = 1; iPF = 2; iPOP = 3; iEIA = 4; iEIF = 5;
        iPROJ = 6; iAGGW = 7; iAGGB = 8; iWL1 = 9; iBL1 = 10; iWR1 = 11;
        iWL2 = 12; iBL2 = 13; iWR2 = 14; iWL3 = 15; iBL3 = 16; iWR3 = 17;
    } else {                  // reference() signature order
        iXI = 0; iXA = 1; iPF = 2; iPROJ = 3; iAGGW = 4; iAGGB = 5;
        iWL1 = 6; iBL1 = 7; iWR1 = 8; iWL2 = 9; iBL2 = 10; iWR2 = 11;
        iWL3 = 12; iBL3 = 13; iWR3 = 14; iPOP = 15; iEIA = 16; iEIF = 17;
    }

    const float* xi   = (const float*)d_in[iXI];
    const float* xa   = (const float*)d_in[iXA];
    const float* pf   = (const float*)d_in[iPF];
    const int*   pop  = (const int*)d_in[iPOP];
    const int*   eia  = (const int*)d_in[iEIA];
    const int*   eif  = (const int*)d_in[iEIF];
    const float* proj = (const float*)d_in[iPROJ];
    const float* aggW = (const float*)d_in[iAGGW];
    const float* aggB = (const float*)d_in[iAGGB];
    const float* wl1  = (const float*)d_in[iWL1];
    const float* bl1  = (const float*)d_in[iBL1];
    const float* wr1  = (const float*)d_in[iWR1];
    const float* wl2  = (const float*)d_in[iWL2];
    const float* bl2  = (const float*)d_in[iBL2];
    const float* wr2  = (const float*)d_in[iWR2];
    const float* wl3  = (const float*)d_in[iWL3];
    const float* bl3  = (const float*)d_in[iBL3];
    const float* wr3  = (const float*)d_in[iWR3];

    float* out = (float*)d_out;  // [x_ind_out (N*D)] then [x_att_out (A*N*D)]

    float *xatt_a, *xatt_b, *agg, *agg3, *cnt, *cnt3, *esf, *wt, *Mbuf;
    cudaGetSymbolAddress((void**)&xatt_a, g_xatt_a);
    cudaGetSymbolAddress((void**)&xatt_b, g_xatt_b);
    cudaGetSymbolAddress((void**)&agg,    g_agg);
    cudaGetSymbolAddress((void**)&agg3,   g_agg3);
    cudaGetSymbolAddress((void**)&cnt,    g_cnt);
    cudaGetSymbolAddress((void**)&cnt3,   g_cnt3);
    cudaGetSymbolAddress((void**)&esf,    g_esf);
    cudaGetSymbolAddress((void**)&wt,     g_wt);
    cudaGetSymbolAddress((void**)&Mbuf,   g_M);

    const int gP = (PP + 127) / 128;  // 391
    const int gN = (NN + 127) / 128;  // 782
    const int sB = (EE + 7) / 8;
    const int sB3 = (EFN + 7) / 8;

    // 0) transposed weights ([i][o] layout)
    transpose_wt<<<1, 256>>>(wt + WT_AGG1, aggW,        256, 0);
    transpose_wt<<<1, 256>>>(wt + WT_AGG2, aggW + 128,  256, 0);
    transpose_wt<<<AA, 256>>>(wt + WT_L1,  wl1, 128, 16384);
    transpose_wt<<<AA, 256>>>(wt + WT_R1,  wr1, 128, 16384);
    transpose_wt<<<AA, 256>>>(wt + WT_L2,  wl2, 128, 16384);
    transpose_wt<<<AA, 256>>>(wt + WT_R2,  wr2, 128, 16384);
    transpose_wt<<<1, 256>>>(wt + WT_L3,   wl3, 128, 0);
    transpose_wt<<<1, 256>>>(wt + WT_R3,   wr3, 128, 0);

    // 1) M = inv(proj) + I
    inv_kernel<<<AA, 256>>>(proj);

    // 2) zero accumulators
    cudaMemsetAsync(agg,  0, AND * sizeof(float), 0);
    cudaMemsetAsync(cnt,  0, (size_t)AA * NN * sizeof(float), 0);
    cudaMemsetAsync(agg3, 0, ND * sizeof(float), 0);
    cudaMemsetAsync(cnt3, 0, (size_t)NN * sizeof(float), 0);

    // 3) esf[a] = PF[:,a,:] @ proj[a]
    for (int a = 0; a < AA; a++)
        gemm128<false, false, false, false, false><<<gP, 256>>>(
            pf + a * DD, AA * DD, proj + (size_t)a * 16384,
            nullptr, nullptr, nullptr, nullptr, nullptr,
            esf + (size_t)a * PD, PP);

    // 4) x_att_a = x_attributes (copy), then overwrite population rows with h
    cudaMemcpyAsync(xatt_a, xa, AND * sizeof(float), cudaMemcpyDeviceToDevice, 0);
    for (int a = 0; a < AA; a++)
        gemm128<true, true, false, true, true><<<gP, 256>>>(
            xa + (size_t)a * ND, DD, wt + WT_AGG1,
            esf + (size_t)a * PD, wt + WT_AGG2,
            aggB, nullptr, pop,
            xatt_a + (size_t)a * ND, PP);

    // 5) agg1: segment-sum of x_individuals[src] over dst
    for (int a = 0; a < AA; a++)
        scatter_add<<<sB, 256>>>(xi,
            eia + (size_t)a * 2 * EE,
            eia + (size_t)a * 2 * EE + EE,
            agg + (size_t)a * ND, cnt + (size_t)a * NN, EE);

    // 6) x_att_b = mean(agg1) @ W_l1^T + b_l1 + x_att_a @ W_r1^T
    for (int a = 0; a < AA; a++)
        gemm128<true, false, true, false, true><<<gN, 256>>>(
            agg + (size_t)a * ND, DD, wt + WT_L1 + (size_t)a * 16384,
            xatt_a + (size_t)a * ND, wt + WT_R1 + (size_t)a * 16384,
            bl1 + a * DD, cnt + (size_t)a * NN, nullptr,
            xatt_b + (size_t)a * ND, NN);

    // 7) population rows: x_att_b[pop] = relu(x_att_b[pop] @ M[a])  (in-place safe)
    for (int a = 0; a < AA; a++)
        gemm128<false, true, false, true, false><<<gP, 256>>>(
            xatt_b + (size_t)a * ND, DD, Mbuf + (size_t)a * 16384,
            nullptr, nullptr, nullptr, nullptr, pop,
            xatt_b + (size_t)a * ND, PP);

    // 8) agg2: segment-sum of x_att_b[dst] over src
    cudaMemsetAsync(agg, 0, AND * sizeof(float), 0);
    cudaMemsetAsync(cnt, 0, (size_t)AA * NN * sizeof(float), 0);
    for (int a = 0; a < AA; a++)
        scatter_add<<<sB, 256>>>(xatt_b + (size_t)a * ND,
            eia + (size_t)a * 2 * EE + EE,
            eia + (size_t)a * 2 * EE,
            agg + (size_t)a * ND, cnt + (size_t)a * NN, EE);

    // 9) x_att_out = mean(agg2) @ W_l2^T + b_l2 + x_att_b @ W_r2^T -> d_out[N*D:]
    for (int a = 0; a < AA; a++)
        gemm128<true, false, true, false, true><<<gN, 256>>>(
            agg + (size_t)a * ND, DD, wt + WT_L2 + (size_t)a * 16384,
            xatt_b + (size_t)a * ND, wt + WT_R2 + (size_t)a * 16384,
            bl2 + a * DD, cnt + (size_t)a * NN, nullptr,
            out + ND + (size_t)a * ND, NN);

    // 10) agg3: family segment-mean of x_individuals[eif[1]] over eif[0]
    scatter_add<<<sB3, 256>>>(xi, eif + EFN, eif, agg3, cnt3, EFN);

    // 11) x_ind_out = mean(agg3) @ W_l3^T + b_l3 + x_individuals @ W_r3^T -> d_out[0:]
    gemm128<true, false, true, false, true><<<gN, 256>>>(
        agg3, DD, wt + WT_L3,
        xi, wt + WT_R3,
        bl3, cnt3, nullptr,
        out, NN);
}

// round 4
// speedup vs baseline: 1.4138x; 1.4138x over previous
#include <cuda_runtime.h>
#include <cstdint>
#include <cstddef>

#define NN 100000
#define DD 128
#define AA 3
#define PP 50000
#define EE 500000
#define EFN 500000

#define ND  ((size_t)NN * DD)
#define AND ((size_t)AA * NN * DD)
#define PD  ((size_t)PP * DD)

// ---------------- scratch (static device globals; no allocation) ----------------
__device__ float  g_xatt_a[AA * NN * DD];
__device__ float  g_xatt_b[AA * NN * DD];
__device__ float  g_agg   [AA * NN * DD];
__device__ float  g_agg3  [NN * DD];
__device__ float  g_cnt   [AA * NN];
__device__ float  g_cnt3  [NN];
__device__ float  g_esf   [AA * PP * DD];
__device__ float  g_projT [AA * 128 * 128];  // proj^T: [o][i]
__device__ double g_inv   [AA * 128 * 256];  // Gauss-Jordan scratch
__device__ float  g_MT    [AA * 128 * 128];  // (inv(proj)+I)^T: [o][i]

// round-to-tf32 (plain PTX, sm_80+; no arch-accelerated features)
__device__ __forceinline__ float tf32r(float x) {
    uint32_t u; asm("cvt.rna.tf32.f32 %0, %1;" : "=r"(u) : "f"(x));
    return __uint_as_float(u);
}

// m16n8k8 tf32 mma (sm_80+ portable)
__device__ __forceinline__ void mma8(float* c, const uint32_t* a, uint32_t b0, uint32_t b1) {
    asm volatile("mma.sync.aligned.m16n8k8.row.col.f32.tf32.tf32.f32 "
                 "{%0,%1,%2,%3}, {%4,%5,%6,%7}, {%8,%9}, {%0,%1,%2,%3};"
                 : "+f"(c[0]), "+f"(c[1]), "+f"(c[2]), "+f"(c[3])
                 : "r"(a[0]), "r"(a[1]), "r"(a[2]), "r"(a[3]), "r"(b0), "r"(b1));
}

// ---------------- weight transpose: dst[b][o][i] = src[b][i][o] -----------------
__global__ void transpose_wt(float* __restrict__ dst, const float* __restrict__ src) {
    int b = blockIdx.x;
    const float* s = src + (size_t)b * 16384;
    float* d = dst + (size_t)b * 16384;
    for (int idx = threadIdx.x; idx < 16384; idx += blockDim.x) {
        int o = idx >> 7, i = idx & 127;
        d[idx] = s[(size_t)i * 128 + o];
    }
}

// ---------------- fp64 Gauss-Jordan; writes (inv(proj)+I)^T ---------------------
__global__ void inv_kernel(const float* __restrict__ proj) {
    int a = blockIdx.x;
    double* A = g_inv + (size_t)a * 128 * 256;
    int tid = threadIdx.x;  // 256 threads

    for (int idx = tid; idx < 128 * 256; idx += 256) {
        int r = idx >> 8, c = idx & 255;
        A[idx] = (c < 128) ? (double)proj[(size_t)a * 16384 + r * 128 + c]
                           : ((c - 128) == r ? 1.0 : 0.0);
    }
    __syncthreads();

    __shared__ double pv[128];
    __shared__ int    pi[128];
    for (int k = 0; k < 128; k++) {
        if (tid < 128) {
            pv[tid] = (tid >= k) ? fabs(A[(size_t)tid * 256 + k]) : -1.0;
            pi[tid] = tid;
        }
        __syncthreads();
        for (int s = 64; s > 0; s >>= 1) {
            if (tid < s && pv[tid + s] > pv[tid]) { pv[tid] = pv[tid + s]; pi[tid] = pi[tid + s]; }
            __syncthreads();
        }
        int piv = pi[0];
        if (piv != k && tid < 256) {
            double t = A[(size_t)k * 256 + tid];
            A[(size_t)k * 256 + tid] = A[(size_t)piv * 256 + tid];
            A[(size_t)piv * 256 + tid] = t;
        }
        __syncthreads();
        double pinv = 1.0 / A[(size_t)k * 256 + k];
        A[(size_t)k * 256 + tid] *= pinv;
        __syncthreads();
        int r = tid >> 1, h = tid & 1;
        double f = (r != k) ? A[(size_t)r * 256 + k] : 0.0;
        __syncthreads();
        if (r != k) {
            int j0 = h * 128;
            #pragma unroll 4
            for (int j = j0; j < j0 + 128; j++)
                A[(size_t)r * 256 + j] -= f * A[(size_t)k * 256 + j];
        }
        __syncthreads();
    }
    // store transposed: MT[o][i] = inv[i][o] + (i==o)
    for (int idx = tid; idx < 16384; idx += 256) {
        int o = idx >> 7, i = idx & 127;
        g_MT[(size_t)a * 16384 + idx] =
            (float)(A[(size_t)i * 256 + 128 + o] + (i == o ? 1.0 : 0.0));
    }
}

// ---------------- edge scatter: agg[si[e]] += data[gi[e]]; cnt[si[e]] += 1 ------
__global__ __launch_bounds__(256)
void scatter_add(const float* __restrict__ data,
                 const int* __restrict__ gi,
                 const int* __restrict__ si,
                 float* __restrict__ agg,
                 float* __restrict__ cnt, int ne) {
    int t = blockIdx.x * blockDim.x + threadIdx.x;
    int w = t >> 5, lane = t & 31;
    if (w >= ne) return;
    int g = gi[w], s = si[w];
    float4 v = ((const float4*)(data + (size_t)g * DD))[lane];
    float* dp = agg + (size_t)s * DD + lane * 4;
    asm volatile("red.global.add.v4.f32 [%0], {%1, %2, %3, %4};"
                 :: "l"(dp), "f"(v.x), "f"(v.y), "f"(v.z), "f"(v.w) : "memory");
    if (lane == 0) atomicAdd(cnt + s, 1.0f);
}

// ---------------- mma.sync tf32 fused GEMM --------------------------------------
// Out[row] = act( scale(row)*In1[row] @ W1^T + In2[row] @ W2^T + bias )
// W given [n][k] K-major (raw weight layout == mma row.col B operand).
// 3-term tf32 split: hi*hi + lo*hi + hi*lo (pre-split at smem fill).
// 512 threads = 16 warps (4x4); warp computes 32 rows x 32 cols via m16n8k8.
// Smem row stride 36 floats -> fragment LDS pattern (4g+tg)%32 conflict-free.
#define ASTRIDE 36
static constexpr int GEMM_SMEM = 2048 + 4 * (128 * ASTRIDE * 4);  // 75776

template<bool HAS2, bool GATHER, bool HASCNT, bool RELU, bool HASBIAS>
__global__ __launch_bounds__(512)
void gemm_tc(const float* __restrict__ In1, int in1Stride,
             const float* __restrict__ W1, int w1Stride,
             const float* __restrict__ In2,
             const float* __restrict__ W2, int w2Stride,
             const float* __restrict__ bias,
             const float* __restrict__ cnt,
             const int*   __restrict__ ridx,
             float* __restrict__ Out, int nrows) {
    extern __shared__ __align__(16) char smem[];
    int*   sRow   = (int*)smem;                 // 128 ints
    float* sScale = (float*)(smem + 512);       // 128 floats
    float* sBias  = (float*)(smem + 1024);      // 128 floats
    float* sAhi = (float*)(smem + 2048);
    float* sAlo = sAhi + 128 * ASTRIDE;
    float* sBhi = sAlo + 128 * ASTRIDE;
    float* sBlo = sBhi + 128 * ASTRIDE;
    const uint32_t* uAhi = (const uint32_t*)sAhi;
    const uint32_t* uAlo = (const uint32_t*)sAlo;
    const uint32_t* uBhi = (const uint32_t*)sBhi;
    const uint32_t* uBlo = (const uint32_t*)sBlo;

    int tid = threadIdx.x, wid = tid >> 5, lane = tid & 31;
    int g = lane >> 2, tg = lane & 3;
    int warpM = wid >> 2, warpN = wid & 3;
    int row0 = blockIdx.x * 128;

    if (tid < 128) {
        int gr = row0 + tid;
        int e = 0; float sc = 0.0f;
        if (gr < nrows) {
            e = GATHER ? ridx[gr] : gr;
            sc = 1.0f;
            if (HASCNT) sc = 1.0f / fmaxf(cnt[e], 1.0f);
        }
        sRow[tid] = e;
        sScale[tid] = sc;
        if (HASBIAS) sBias[tid] = bias[tid];
    }
    __syncthreads();

    float acc[2][4][4];
    #pragma unroll
    for (int mt = 0; mt < 2; mt++)
        #pragma unroll
        for (int nt = 0; nt < 4; nt++)
            #pragma unroll
            for (int i = 0; i < 4; i++) acc[mt][nt][i] = 0.0f;

    const int nops = HAS2 ? 2 : 1;

    for (int op = 0; op < nops; op++) {
        const float* Ain = (op == 0) ? In1 : In2;
        int Ast          = (op == 0) ? in1Stride : 128;
        const float* Bw  = (op == 0) ? W1 : W2;
        int Bst          = (op == 0) ? w1Stride : w2Stride;

        for (int kc = 0; kc < 128; kc += 32) {
            // ---- fill A and B chunks (128 x 32 each), hi/lo tf32 split ----
            #pragma unroll
            for (int q = 0; q < 2; q++) {
                int idx = tid * 2 + q;          // 0..1023
                int rr = idx >> 3, seg = idx & 7;
                // A
                const float* src; float sc;
                if (op == 0) { src = Ain + (size_t)sRow[rr] * Ast + kc + seg * 4; sc = sScale[rr]; }
                else {
                    int g2 = row0 + rr; if (g2 >= nrows) g2 = nrows - 1;
                    src = Ain + (size_t)g2 * 128 + kc + seg * 4; sc = 1.0f;
                }
                float4 v = *(const float4*)src;
                v.x *= sc; v.y *= sc; v.z *= sc; v.w *= sc;
                float4 hi, lo;
                hi.x = tf32r(v.x); lo.x = tf32r(v.x - hi.x);
                hi.y = tf32r(v.y); lo.y = tf32r(v.y - hi.y);
                hi.z = tf32r(v.z); lo.z = tf32r(v.z - hi.z);
                hi.w = tf32r(v.w); lo.w = tf32r(v.w - hi.w);
                *(float4*)(sAhi + rr * ASTRIDE + seg * 4) = hi;
                *(float4*)(sAlo + rr * ASTRIDE + seg * 4) = lo;
                // B (row n = rr)
                const float* bs = Bw + (size_t)rr * Bst + kc + seg * 4;
                float4 w = *(const float4*)bs;
                float4 whi, wlo;
                whi.x = tf32r(w.x); wlo.x = tf32r(w.x - whi.x);
                whi.y = tf32r(w.y); wlo.y = tf32r(w.y - whi.y);
                whi.z = tf32r(w.z); wlo.z = tf32r(w.z - whi.z);
                whi.w = tf32r(w.w); wlo.w = tf32r(w.w - whi.w);
                *(float4*)(sBhi + rr * ASTRIDE + seg * 4) = whi;
                *(float4*)(sBlo + rr * ASTRIDE + seg * 4) = wlo;
            }
            __syncthreads();

            // ---- compute: 4 k8-steps over this 32-wide chunk ----
            #pragma unroll
            for (int ks = 0; ks < 4; ks++) {
                int kk = ks * 8 + tg;
                uint32_t ah[2][4], al[2][4];
                #pragma unroll
                for (int mt = 0; mt < 2; mt++) {
                    int rb = (warpM * 32 + mt * 16 + g) * ASTRIDE;
                    ah[mt][0] = uAhi[rb + kk];
                    ah[mt][1] = uAhi[rb + 8 * ASTRIDE + kk];
                    ah[mt][2] = uAhi[rb + kk + 4];
                    ah[mt][3] = uAhi[rb + 8 * ASTRIDE + kk + 4];
                    al[mt][0] = uAlo[rb + kk];
                    al[mt][1] = uAlo[rb + 8 * ASTRIDE + kk];
                    al[mt][2] = uAlo[rb + kk + 4];
                    al[mt][3] = uAlo[rb + 8 * ASTRIDE + kk + 4];
                }
                #pragma unroll
                for (int nt = 0; nt < 4; nt++) {
                    int nb = (warpN * 32 + nt * 8 + g) * ASTRIDE;
                    uint32_t bh0 = uBhi[nb + kk], bh1 = uBhi[nb + kk + 4];
                    uint32_t bl0 = uBlo[nb + kk], bl1 = uBlo[nb + kk + 4];
                    #pragma unroll
                    for (int mt = 0; mt < 2; mt++) {
                        mma8(acc[mt][nt], ah[mt], bh0, bh1);
                        mma8(acc[mt][nt], al[mt], bh0, bh1);
                        mma8(acc[mt][nt], ah[mt], bl0, bl1);
                    }
                }
            }
            __syncthreads();
        }
    }

    // ---- epilogue ----
    #pragma unroll
    for (int mt = 0; mt < 2; mt++) {
        #pragma unroll
        for (int half = 0; half < 2; half++) {
            int lr = warpM * 32 + mt * 16 + g + half * 8;
            int grow = row0 + lr;
            if (grow < nrows) {
                int orow = GATHER ? sRow[lr] : grow;
                float* ob = Out + (size_t)orow * 128;
                #pragma unroll
                for (int nt = 0; nt < 4; nt++) {
                    int col = warpN * 32 + nt * 8 + tg * 2;
                    float v0 = acc[mt][nt][half * 2 + 0];
                    float v1 = acc[mt][nt][half * 2 + 1];
                    if (HASBIAS) { v0 += sBias[col]; v1 += sBias[col + 1]; }
                    if (RELU) { v0 = fmaxf(v0, 0.0f); v1 = fmaxf(v1, 0.0f); }
                    float2 p; p.x = v0; p.y = v1;
                    *(float2*)(ob + col) = p;
                }
            }
        }
    }
}

// ---------------- host orchestration -------------------------------------------
extern "C" void kernel_launch(void* const* d_in, const int* in_sizes, int n_in,
                              void* d_out, int out_size) {
    int iXI, iXA, iPF, iPOP, iEIA, iEIF, iPROJ, iAGGW, iAGGB,
        iWL1, iBL1, iWR1, iWL2, iBL2, iWR2, iWL3, iBL3, iWR3;
    if (in_sizes[3] == PP) {  // setup_inputs dict order
        iXI = 0; iXA = 1; iPF = 2; iPOP = 3; iEIA = 4; iEIF = 5;
        iPROJ = 6; iAGGW = 7; iAGGB = 8; iWL1 = 9; iBL1 = 10; iWR1 = 11;
        iWL2 = 12; iBL2 = 13; iWR2 = 14; iWL3 = 15; iBL3 = 16; iWR3 = 17;
    } else {                  // reference() signature order
        iXI = 0; iXA = 1; iPF = 2; iPROJ = 3; iAGGW = 4; iAGGB = 5;
        iWL1 = 6; iBL1 = 7; iWR1 = 8; iWL2 = 9; iBL2 = 10; iWR2 = 11;
        iWL3 = 12; iBL3 = 13; iWR3 = 14; iPOP = 15; iEIA = 16; iEIF = 17;
    }

    const float* xi   = (const float*)d_in[iXI];
    const float* xa   = (const float*)d_in[iXA];
    const float* pf   = (const float*)d_in[iPF];
    const int*   pop  = (const int*)d_in[iPOP];
    const int*   eia  = (const int*)d_in[iEIA];
    const int*   eif  = (const int*)d_in[iEIF];
    const float* proj = (const float*)d_in[iPROJ];
    const float* aggW = (const float*)d_in[iAGGW];
    const float* aggB = (const float*)d_in[iAGGB];
    const float* wl1  = (const float*)d_in[iWL1];
    const float* bl1  = (const float*)d_in[iBL1];
    const float* wr1  = (const float*)d_in[iWR1];
    const float* wl2  = (const float*)d_in[iWL2];
    const float* bl2  = (const float*)d_in[iBL2];
    const float* wr2  = (const float*)d_in[iWR2];
    const float* wl3  = (const float*)d_in[iWL3];
    const float* bl3  = (const float*)d_in[iBL3];
    const float* wr3  = (const float*)d_in[iWR3];

    float* out = (float*)d_out;  // [x_ind_out (N*D)] then [x_att_out (A*N*D)]

    float *xatt_a, *xatt_b, *agg, *agg3, *cnt, *cnt3, *esf, *projT, *MT;
    cudaGetSymbolAddress((void**)&xatt_a, g_xatt_a);
    cudaGetSymbolAddress((void**)&xatt_b, g_xatt_b);
    cudaGetSymbolAddress((void**)&agg,    g_agg);
    cudaGetSymbolAddress((void**)&agg3,   g_agg3);
    cudaGetSymbolAddress((void**)&cnt,    g_cnt);
    cudaGetSymbolAddress((void**)&cnt3,   g_cnt3);
    cudaGetSymbolAddress((void**)&esf,    g_esf);
    cudaGetSymbolAddress((void**)&projT,  g_projT);
    cudaGetSymbolAddress((void**)&MT,     g_MT);

    cudaFuncSetAttribute(gemm_tc<false, false, false, false, false>,
                         cudaFuncAttributeMaxDynamicSharedMemorySize, GEMM_SMEM);
    cudaFuncSetAttribute(gemm_tc<true, true, false, true, true>,
                         cudaFuncAttributeMaxDynamicSharedMemorySize, GEMM_SMEM);
    cudaFuncSetAttribute(gemm_tc<true, false, true, false, true>,
                         cudaFuncAttributeMaxDynamicSharedMemorySize, GEMM_SMEM);
    cudaFuncSetAttribute(gemm_tc<false, true, false, true, false>,
                         cudaFuncAttributeMaxDynamicSharedMemorySize, GEMM_SMEM);

    const int gP = (PP + 127) / 128;  // 391
    const int gN = (NN + 127) / 128;  // 782
    const int sB = (EE + 7) / 8;
    const int sB3 = (EFN + 7) / 8;

    // 0) projT; 1) MT = (inv(proj)+I)^T
    transpose_wt<<<AA, 256>>>(projT, proj);
    inv_kernel<<<AA, 256>>>(proj);

    // 2) zero accumulators
    cudaMemsetAsync(agg,  0, AND * sizeof(float), 0);
    cudaMemsetAsync(cnt,  0, (size_t)AA * NN * sizeof(float), 0);
    cudaMemsetAsync(agg3, 0, ND * sizeof(float), 0);
    cudaMemsetAsync(cnt3, 0, (size_t)NN * sizeof(float), 0);

    // 3) esf[a] = PF[:,a,:] @ proj[a]  (B = projT, [o][i])
    for (int a = 0; a < AA; a++)
        gemm_tc<false, false, false, false, false><<<gP, 512, GEMM_SMEM>>>(
            pf + (size_t)a * DD, AA * DD, projT + (size_t)a * 16384, 128,
            nullptr, nullptr, 0, nullptr, nullptr, nullptr,
            esf + (size_t)a * PD, PP);

    // 4) x_att_a = copy(xa); population rows = relu([xa[pop], esf] @ aggW^T + b)
    cudaMemcpyAsync(xatt_a, xa, AND * sizeof(float), cudaMemcpyDeviceToDevice, 0);
    for (int a = 0; a < AA; a++)
        gemm_tc<true, true, false, true, true><<<gP, 512, GEMM_SMEM>>>(
            xa + (size_t)a * ND, DD, aggW, 256,
            esf + (size_t)a * PD, aggW + 128, 256,
            aggB, nullptr, pop,
            xatt_a + (size_t)a * ND, PP);

    // 5) agg1: segment-sum of x_individuals[src] over dst
    for (int a = 0; a < AA; a++)
        scatter_add<<<sB, 256>>>(xi,
            eia + (size_t)a * 2 * EE,
            eia + (size_t)a * 2 * EE + EE,
            agg + (size_t)a * ND, cnt + (size_t)a * NN, EE);

    // 6) x_att_b = mean(agg1) @ W_l1^T + b_l1 + x_att_a @ W_r1^T
    for (int a = 0; a < AA; a++)
        gemm_tc<true, false, true, false, true><<<gN, 512, GEMM_SMEM>>>(
            agg + (size_t)a * ND, DD, wl1 + (size_t)a * 16384, 128,
            xatt_a + (size_t)a * ND, wr1 + (size_t)a * 16384, 128,
            bl1 + (size_t)a * DD, cnt + (size_t)a * NN, nullptr,
            xatt_b + (size_t)a * ND, NN);

    // 7) population rows: x_att_b[pop] = relu(x_att_b[pop] @ (inv(proj)+I))
    for (int a = 0; a < AA; a++)
        gemm_tc<false, true, false, true, false><<<gP, 512, GEMM_SMEM>>>(
            xatt_b + (size_t)a * ND, DD, MT + (size_t)a * 16384, 128,
            nullptr, nullptr, 0, nullptr, nullptr, pop,
            xatt_b + (size_t)a * ND, PP);

    // 8) agg2: segment-sum of x_att_b[dst] over src
    cudaMemsetAsync(agg, 0, AND * sizeof(float), 0);
    cudaMemsetAsync(cnt, 0, (size_t)AA * NN * sizeof(float), 0);
    for (int a = 0; a < AA; a++)
        scatter_add<<<sB, 256>>>(xatt_b + (size_t)a * ND,
            eia + (size_t)a * 2 * EE + EE,
            eia + (size_t)a * 2 * EE,
            agg + (size_t)a * ND, cnt + (size_t)a * NN, EE);

    // 9) x_att_out = mean(agg2) @ W_l2^T + b_l2 + x_att_b @ W_r2^T  -> d_out[N*D:]
    for (int a = 0; a < AA; a++)
        gemm_tc<true, false, true, false, true><<<gN, 512, GEMM_SMEM>>>(
            agg + (size_t)a * ND, DD, wl2 + (size_t)a * 16384, 128,
            xatt_b + (size_t)a * ND, wr2 + (size_t)a * 16384, 128,
            bl2 + (size_t)a * DD, cnt + (size_t)a * NN, nullptr,
            out + ND + (size_t)a * ND, NN);

    // 10) agg3: family segment-mean of x_individuals[eif[1]] over eif[0]
    scatter_add<<<sB3, 256>>>(xi, eif + EFN, eif, agg3, cnt3, EFN);

    // 11) x_ind_out = mean(agg3) @ W_l3^T + b_l3 + x_individuals @ W_r3^T -> d_out[0:]
    gemm_tc<true, false, true, false, true><<<gN, 512, GEMM_SMEM>>>(
        agg3, DD, wl3, 128,
        xi, wr3, 128,
        bl3, cnt3, nullptr,
        out, NN);
}

// round 5
// speedup vs baseline: 1.4849x; 1.0503x over previous
#include <cuda_runtime.h>
#include <cstdint>
#include <cstddef>

#define NN 100000
#define DD 128
#define AA 3
#define PP 50000
#define EE 500000
#define EFN 500000

#define ND  ((size_t)NN * DD)
#define AND ((size_t)AA * NN * DD)
#define PD  ((size_t)PP * DD)

// ---------------- scratch (static device globals; no allocation) ----------------
__device__ float  g_xatt_a[AA * NN * DD];
__device__ float  g_xatt_b[AA * NN * DD];
__device__ float  g_agg   [AA * NN * DD];
__device__ float  g_agg3  [NN * DD];
__device__ float  g_esf   [AA * PP * DD];
__device__ float  g_projT [AA * 128 * 128];  // proj^T: [o][i]
__device__ double g_inv   [AA * 128 * 256];  // Gauss-Jordan scratch
__device__ float  g_MT    [AA * 128 * 128];  // (inv(proj)+I)^T: [o][i]
// CSR structures for the 7 edge graphs (0-2: attr dst-seg, 3-5: attr src-seg, 6: family)
__device__ int    g_rowptr[7 * (NN + 1)];
__device__ int    g_fill  [7 * NN];          // histogram, then fill cursors
__device__ int    g_eord  [7 * EE];          // gather indices ordered by segment

// round-to-tf32 (plain PTX, sm_80+)
__device__ __forceinline__ float tf32r(float x) {
    uint32_t u; asm("cvt.rna.tf32.f32 %0, %1;" : "=r"(u) : "f"(x));
    return __uint_as_float(u);
}
// m16n8k8 tf32 mma (sm_80+ portable)
__device__ __forceinline__ void mma8(float* c, const uint32_t* a, uint32_t b0, uint32_t b1) {
    asm volatile("mma.sync.aligned.m16n8k8.row.col.f32.tf32.tf32.f32 "
                 "{%0,%1,%2,%3}, {%4,%5,%6,%7}, {%8,%9}, {%0,%1,%2,%3};"
                 : "+f"(c[0]), "+f"(c[1]), "+f"(c[2]), "+f"(c[3])
                 : "r"(a[0]), "r"(a[1]), "r"(a[2]), "r"(a[3]), "r"(b0), "r"(b1));
}

// ---------------- weight transpose: dst[b][o][i] = src[b][i][o] -----------------
__global__ void transpose_wt(float* __restrict__ dst, const float* __restrict__ src) {
    int b = blockIdx.x;
    const float* s = src + (size_t)b * 16384;
    float* d = dst + (size_t)b * 16384;
    for (int idx = threadIdx.x; idx < 16384; idx += blockDim.x) {
        int o = idx >> 7, i = idx & 127;
        d[idx] = s[(size_t)i * 128 + o];
    }
}

// ---------------- fp64 Gauss-Jordan; writes (inv(proj)+I)^T ---------------------
__global__ void inv_kernel(const float* __restrict__ proj) {
    int a = blockIdx.x;
    double* A = g_inv + (size_t)a * 128 * 256;
    int tid = threadIdx.x;  // 256 threads

    for (int idx = tid; idx < 128 * 256; idx += 256) {
        int r = idx >> 8, c = idx & 255;
        A[idx] = (c < 128) ? (double)proj[(size_t)a * 16384 + r * 128 + c]
                           : ((c - 128) == r ? 1.0 : 0.0);
    }
    __syncthreads();

    __shared__ double pv[128];
    __shared__ int    pi[128];
    for (int k = 0; k < 128; k++) {
        if (tid < 128) {
            pv[tid] = (tid >= k) ? fabs(A[(size_t)tid * 256 + k]) : -1.0;
            pi[tid] = tid;
        }
        __syncthreads();
        for (int s = 64; s > 0; s >>= 1) {
            if (tid < s && pv[tid + s] > pv[tid]) { pv[tid] = pv[tid + s]; pi[tid] = pi[tid + s]; }
            __syncthreads();
        }
        int piv = pi[0];
        if (piv != k && tid < 256) {
            double t = A[(size_t)k * 256 + tid];
            A[(size_t)k * 256 + tid] = A[(size_t)piv * 256 + tid];
            A[(size_t)piv * 256 + tid] = t;
        }
        __syncthreads();
        double pinv = 1.0 / A[(size_t)k * 256 + k];
        A[(size_t)k * 256 + tid] *= pinv;
        __syncthreads();
        int r = tid >> 1, h = tid & 1;
        double f = (r != k) ? A[(size_t)r * 256 + k] : 0.0;
        __syncthreads();
        if (r != k) {
            int j0 = h * 128;
            #pragma unroll 4
            for (int j = j0; j < j0 + 128; j++)
                A[(size_t)r * 256 + j] -= f * A[(size_t)k * 256 + j];
        }
        __syncthreads();
    }
    for (int idx = tid; idx < 16384; idx += 256) {
        int o = idx >> 7, i = idx & 127;
        g_MT[(size_t)a * 16384 + idx] =
            (float)(A[(size_t)i * 256 + 128 + o] + (i == o ? 1.0 : 0.0));
    }
}

// ---------------- CSR build ------------------------------------------------------
// graph g: 0-2 -> seg=dst(a=g), gather=src ; 3-5 -> seg=src(a=g-3), gather=dst ;
//          6 -> seg=eif[0], gather=eif[1]
__device__ __forceinline__ void graph_ptrs(int g, const int* eia, const int* eif,
                                           const int** gi, const int** si) {
    if (g < 3)      { *gi = eia + (size_t)g * 2 * EE;            *si = eia + (size_t)g * 2 * EE + EE; }
    else if (g < 6) { *gi = eia + (size_t)(g - 3) * 2 * EE + EE; *si = eia + (size_t)(g - 3) * 2 * EE; }
    else            { *gi = eif + EFN;                           *si = eif; }
}

__global__ void hist_k(const int* __restrict__ eia, const int* __restrict__ eif) {
    int g = blockIdx.y;
    const int *gi, *si;
    graph_ptrs(g, eia, eif, &gi, &si);
    int e = blockIdx.x * blockDim.x + threadIdx.x;
    if (e < EE) atomicAdd(g_fill + (size_t)g * NN + si[e], 1);
}

// single block of 1024 threads per graph: exclusive scan of counts -> rowptr,
// and reset g_fill[i] to the start offset (fill cursor).
__global__ __launch_bounds__(1024)
void scan_k() {
    int g = blockIdx.x;
    int* cnt = g_fill + (size_t)g * NN;      // will be overwritten with cursors
    int* rp  = g_rowptr + (size_t)g * (NN + 1);
    __shared__ int partial[1024];
    int tid = threadIdx.x;
    const int chunk = (NN + 1023) / 1024;
    int s = tid * chunk, e = s + chunk; if (e > NN) e = NN; if (s > NN) s = NN;
    int sum = 0;
    for (int i = s; i < e; i++) sum += cnt[i];
    partial[tid] = sum;
    __syncthreads();
    for (int off = 1; off < 1024; off <<= 1) {
        int v = (tid >= off) ? partial[tid - off] : 0;
        __syncthreads();
        partial[tid] += v;
        __syncthreads();
    }
    int base = (tid == 0) ? 0 : partial[tid - 1];
    for (int i = s; i < e; i++) {
        int c = cnt[i];
        rp[i] = base;
        cnt[i] = base;     // cursor
        base += c;
    }
    if (tid == 1023) rp[NN] = base;
}

__global__ void fill_k(const int* __restrict__ eia, const int* __restrict__ eif) {
    int g = blockIdx.y;
    const int *gi, *si;
    graph_ptrs(g, eia, eif, &gi, &si);
    int e = blockIdx.x * blockDim.x + threadIdx.x;
    if (e < EE) {
        int pos = atomicAdd(g_fill + (size_t)g * NN + si[e], 1);
        g_eord[(size_t)g * EE + pos] = gi[e];
    }
}

// ---------------- gather-mean: out[n] = mean_{j in CSR[n]} data[eord[j]] --------
// warp per node; lane owns one float4 column slice. graph = gbase + blockIdx.y.
__global__ __launch_bounds__(256)
void gather_mean(const float* __restrict__ data, long dataBStr,
                 int gbase, float* __restrict__ outp, long outBStr) {
    int a = blockIdx.y;
    int g = gbase + a;
    const float* d = data + (size_t)a * dataBStr;
    float* o = outp + (size_t)a * outBStr;
    const int* rp = g_rowptr + (size_t)g * (NN + 1);
    const int* eo = g_eord + (size_t)g * EE;

    int node = blockIdx.x * 8 + (threadIdx.x >> 5);
    int lane = threadIdx.x & 31;
    if (node >= NN) return;
    int s = rp[node], e = rp[node + 1];
    float4 acc = make_float4(0.f, 0.f, 0.f, 0.f);
    int j = s;
    for (; j + 1 < e; j += 2) {
        int g0 = eo[j], g1 = eo[j + 1];
        float4 v0 = ((const float4*)(d + (size_t)g0 * DD))[lane];
        float4 v1 = ((const float4*)(d + (size_t)g1 * DD))[lane];
        acc.x += v0.x + v1.x; acc.y += v0.y + v1.y;
        acc.z += v0.z + v1.z; acc.w += v0.w + v1.w;
    }
    if (j < e) {
        float4 v = ((const float4*)(d + (size_t)eo[j] * DD))[lane];
        acc.x += v.x; acc.y += v.y; acc.z += v.z; acc.w += v.w;
    }
    float inv = 1.0f / fmaxf((float)(e - s), 1.0f);
    acc.x *= inv; acc.y *= inv; acc.z *= inv; acc.w *= inv;
    ((float4*)(o + (size_t)node * DD))[lane] = acc;
}

// ---------------- mma.sync tf32 fused GEMM (pipelined, batched over y) ----------
// Out[row] = act( In1[row] @ W1^T + In2[row] @ W2^T + bias ), rows gathered if GATHER.
// 3-term tf32 split; register-prefetch of next chunk's global loads overlaps mma.
#define ASTRIDE 36
static constexpr int GEMM_SMEM = 1024 + 4 * (128 * ASTRIDE * 4);  // 74752

template<bool HAS2, bool GATHER, bool RELU, bool HASBIAS>
__global__ __launch_bounds__(512)
void gemm_tc(const float* __restrict__ In1, int in1Stride, long in1BStr,
             const float* __restrict__ W1, int w1Stride, long w1BStr,
             const float* __restrict__ In2, long in2BStr,
             const float* __restrict__ W2, int w2Stride, long w2BStr,
             const float* __restrict__ bias, long biasBStr,
             const int*   __restrict__ ridx,
             float* __restrict__ Out, long outBStr, int nrows) {
    extern __shared__ __align__(16) char smem[];
    int*   sRow  = (int*)smem;                  // 128 ints
    float* sBias = (float*)(smem + 512);        // 128 floats
    float* sAhi = (float*)(smem + 1024);
    float* sAlo = sAhi + 128 * ASTRIDE;
    float* sBhi = sAlo + 128 * ASTRIDE;
    float* sBlo = sBhi + 128 * ASTRIDE;
    const uint32_t* uAhi = (const uint32_t*)sAhi;
    const uint32_t* uAlo = (const uint32_t*)sAlo;
    const uint32_t* uBhi = (const uint32_t*)sBhi;
    const uint32_t* uBlo = (const uint32_t*)sBlo;

    {   // per-attribute (blockIdx.y) pointer offsets
        long a = blockIdx.y;
        In1 += a * in1BStr; W1 += a * w1BStr;
        if (HAS2) { In2 += a * in2BStr; W2 += a * w2BStr; }
        if (HASBIAS) bias += a * biasBStr;
        Out += a * outBStr;
    }

    int tid = threadIdx.x, wid = tid >> 5, lane = tid & 31;
    int g = lane >> 2, tg = lane & 3;
    int warpM = wid >> 2, warpN = wid & 3;
    int row0 = blockIdx.x * 128;

    if (tid < 128) {
        int gr = row0 + tid;
        int e = 0;
        if (gr < nrows) e = GATHER ? ridx[gr] : gr;
        sRow[tid] = e;
        if (HASBIAS) sBias[tid] = bias[tid];
    }
    __syncthreads();

    float acc[2][4][4];
    #pragma unroll
    for (int mt = 0; mt < 2; mt++)
        #pragma unroll
        for (int nt = 0; nt < 4; nt++)
            #pragma unroll
            for (int i = 0; i < 4; i++) acc[mt][nt][i] = 0.0f;

    const int np = HAS2 ? 8 : 4;
    float4 rA[2], rB[2];

    auto loadph = [&](int p) {
        int op = HAS2 ? (p >> 2) : 0;
        int kc = (p & 3) * 32;
        #pragma unroll
        for (int q = 0; q < 2; q++) {
            int idx = tid * 2 + q;
            int rr = idx >> 3, seg = idx & 7;
            const float* asrc;
            if (op == 0) asrc = In1 + (size_t)sRow[rr] * in1Stride + kc + seg * 4;
            else {
                int g2 = row0 + rr; if (g2 >= nrows) g2 = nrows - 1;
                asrc = In2 + (size_t)g2 * 128 + kc + seg * 4;
            }
            rA[q] = *(const float4*)asrc;
            const float* bw = (op == 0) ? W1 : W2;
            int bst = (op == 0) ? w1Stride : w2Stride;
            rB[q] = *(const float4*)(bw + (size_t)rr * bst + kc + seg * 4);
        }
    };
    auto storeph = [&]() {
        #pragma unroll
        for (int q = 0; q < 2; q++) {
            int idx = tid * 2 + q;
            int rr = idx >> 3, seg = idx & 7;
            float4 v = rA[q];
            float4 hi, lo;
            hi.x = tf32r(v.x); lo.x = tf32r(v.x - hi.x);
            hi.y = tf32r(v.y); lo.y = tf32r(v.y - hi.y);
            hi.z = tf32r(v.z); lo.z = tf32r(v.z - hi.z);
            hi.w = tf32r(v.w); lo.w = tf32r(v.w - hi.w);
            *(float4*)(sAhi + rr * ASTRIDE + seg * 4) = hi;
            *(float4*)(sAlo + rr * ASTRIDE + seg * 4) = lo;
            float4 w = rB[q];
            float4 whi, wlo;
            whi.x = tf32r(w.x); wlo.x = tf32r(w.x - whi.x);
            whi.y = tf32r(w.y); wlo.y = tf32r(w.y - whi.y);
            whi.z = tf32r(w.z); wlo.z = tf32r(w.z - whi.z);
            whi.w = tf32r(w.w); wlo.w = tf32r(w.w - whi.w);
            *(float4*)(sBhi + rr * ASTRIDE + seg * 4) = whi;
            *(float4*)(sBlo + rr * ASTRIDE + seg * 4) = wlo;
        }
    };

    loadph(0);
    for (int p = 0; p < np; p++) {
        storeph();
        __syncthreads();
        if (p + 1 < np) loadph(p + 1);   // overlap next chunk's DRAM latency with mma
        #pragma unroll
        for (int ks = 0; ks < 4; ks++) {
            int kk = ks * 8 + tg;
            uint32_t ah[2][4], al[2][4];
            #pragma unroll
            for (int mt = 0; mt < 2; mt++) {
                int rb = (warpM * 32 + mt * 16 + g) * ASTRIDE;
                ah[mt][0] = uAhi[rb + kk];
                ah[mt][1] = uAhi[rb + 8 * ASTRIDE + kk];
                ah[mt][2] = uAhi[rb + kk + 4];
                ah[mt][3] = uAhi[rb + 8 * ASTRIDE + kk + 4];
                al[mt][0] = uAlo[rb + kk];
                al[mt][1] = uAlo[rb + 8 * ASTRIDE + kk];
                al[mt][2] = uAlo[rb + kk + 4];
                al[mt][3] = uAlo[rb + 8 * ASTRIDE + kk + 4];
            }
            #pragma unroll
            for (int nt = 0; nt < 4; nt++) {
                int nb = (warpN * 32 + nt * 8 + g) * ASTRIDE;
                uint32_t bh0 = uBhi[nb + kk], bh1 = uBhi[nb + kk + 4];
                uint32_t bl0 = uBlo[nb + kk], bl1 = uBlo[nb + kk + 4];
                #pragma unroll
                for (int mt = 0; mt < 2; mt++) {
                    mma8(acc[mt][nt], ah[mt], bh0, bh1);
                    mma8(acc[mt][nt], al[mt], bh0, bh1);
                    mma8(acc[mt][nt], ah[mt], bl0, bl1);
                }
            }
        }
        __syncthreads();
    }

    // ---- epilogue ----
    #pragma unroll
    for (int mt = 0; mt < 2; mt++) {
        #pragma unroll
        for (int half = 0; half < 2; half++) {
            int lr = warpM * 32 + mt * 16 + g + half * 8;
            int grow = row0 + lr;
            if (grow < nrows) {
                int orow = GATHER ? sRow[lr] : grow;
                float* ob = Out + (size_t)orow * 128;
                #pragma unroll
                for (int nt = 0; nt < 4; nt++) {
                    int col = warpN * 32 + nt * 8 + tg * 2;
                    float v0 = acc[mt][nt][half * 2 + 0];
                    float v1 = acc[mt][nt][half * 2 + 1];
                    if (HASBIAS) { v0 += sBias[col]; v1 += sBias[col + 1]; }
                    if (RELU) { v0 = fmaxf(v0, 0.0f); v1 = fmaxf(v1, 0.0f); }
                    float2 pp; pp.x = v0; pp.y = v1;
                    *(float2*)(ob + col) = pp;
                }
            }
        }
    }
}

// ---------------- host orchestration -------------------------------------------
extern "C" void kernel_launch(void* const* d_in, const int* in_sizes, int n_in,
                              void* d_out, int out_size) {
    int iXI, iXA, iPF, iPOP, iEIA, iEIF, iPROJ, iAGGW, iAGGB,
        iWL1, iBL1, iWR1, iWL2, iBL2, iWR2, iWL3, iBL3, iWR3;
    if (in_sizes[3] == PP) {  // setup_inputs dict order
        iXI = 0; iXA = 1; iPF = 2; iPOP = 3; iEIA = 4; iEIF = 5;
        iPROJ = 6; iAGGW = 7; iAGGB = 8; iWL1 = 9; iBL1 = 10; iWR1 = 11;
        iWL2 = 12; iBL2 = 13; iWR2 = 14; iWL3 = 15; iBL3 = 16; iWR3 = 17;
    } else {                  // reference() signature order
        iXI = 0; iXA = 1; iPF = 2; iPROJ = 3; iAGGW = 4; iAGGB = 5;
        iWL1 = 6; iBL1 = 7; iWR1 = 8; iWL2 = 9; iBL2 = 10; iWR2 = 11;
        iWL3 = 12; iBL3 = 13; iWR3 = 14; iPOP = 15; iEIA = 16; iEIF = 17;
    }

    const float* xi   = (const float*)d_in[iXI];
    const float* xa   = (const float*)d_in[iXA];
    const float* pf   = (const float*)d_in[iPF];
    const int*   pop  = (const int*)d_in[iPOP];
    const int*   eia  = (const int*)d_in[iEIA];
    const int*   eif  = (const int*)d_in[iEIF];
    const float* proj = (const float*)d_in[iPROJ];
    const float* aggW = (const float*)d_in[iAGGW];
    const float* aggB = (const float*)d_in[iAGGB];
    const float* wl1  = (const float*)d_in[iWL1];
    const float* bl1  = (const float*)d_in[iBL1];
    const float* wr1  = (const float*)d_in[iWR1];
    const float* wl2  = (const float*)d_in[iWL2];
    const float* bl2  = (const float*)d_in[iBL2];
    const float* wr2  = (const float*)d_in[iWR2];
    const float* wl3  = (const float*)d_in[iWL3];
    const float* bl3  = (const float*)d_in[iBL3];
    const float* wr3  = (const float*)d_in[iWR3];

    float* out = (float*)d_out;  // [x_ind_out (N*D)] then [x_att_out (A*N*D)]

    float *xatt_a, *xatt_b, *agg, *agg3, *esf, *projT, *MT;
    int *fillp;
    cudaGetSymbolAddress((void**)&xatt_a, g_xatt_a);
    cudaGetSymbolAddress((void**)&xatt_b, g_xatt_b);
    cudaGetSymbolAddress((void**)&agg,    g_agg);
    cudaGetSymbolAddress((void**)&agg3,   g_agg3);
    cudaGetSymbolAddress((void**)&esf,    g_esf);
    cudaGetSymbolAddress((void**)&projT,  g_projT);
    cudaGetSymbolAddress((void**)&MT,     g_MT);
    cudaGetSymbolAddress((void**)&fillp,  g_fill);

    cudaFuncSetAttribute(gemm_tc<false, false, false, false>,
                         cudaFuncAttributeMaxDynamicSharedMemorySize, GEMM_SMEM);
    cudaFuncSetAttribute(gemm_tc<true, true, true, true>,
                         cudaFuncAttributeMaxDynamicSharedMemorySize, GEMM_SMEM);
    cudaFuncSetAttribute(gemm_tc<true, false, false, true>,
                         cudaFuncAttributeMaxDynamicSharedMemorySize, GEMM_SMEM);
    cudaFuncSetAttribute(gemm_tc<false, true, true, false>,
                         cudaFuncAttributeMaxDynamicSharedMemorySize, GEMM_SMEM);

    const int gP = (PP + 127) / 128;  // 391
    const int gN = (NN + 127) / 128;  // 782
    const int eB = (EE + 255) / 256;  // edge blocks
    const int nB = (NN + 7) / 8;      // gather blocks (8 warps/block)

    // --- prep: transposes + inverse ---
    transpose_wt<<<AA, 256>>>(projT, proj);
    inv_kernel<<<AA, 256>>>(proj);

    // --- CSR build for all 7 graphs ---
    cudaMemsetAsync(fillp, 0, (size_t)7 * NN * sizeof(int), 0);
    hist_k<<<dim3(eB, 7), 256>>>(eia, eif);
    scan_k<<<7, 1024>>>();
    fill_k<<<dim3(eB, 7), 256>>>(eia, eif);

    // 3) esf[a] = PF[:,a,:] @ proj[a]
    gemm_tc<false, false, false, false><<<dim3(gP, AA), 512, GEMM_SMEM>>>(
        pf, AA * DD, DD, projT, 128, 16384,
        nullptr, 0, nullptr, 0, 0, nullptr, 0, nullptr,
        esf, (long)PD, PP);

    // 4) x_att_a = copy(xa); population rows = relu([xa[pop], esf] @ aggW^T + b)
    cudaMemcpyAsync(xatt_a, xa, AND * sizeof(float), cudaMemcpyDeviceToDevice, 0);
    gemm_tc<true, true, true, true><<<dim3(gP, AA), 512, GEMM_SMEM>>>(
        xa, DD, (long)ND, aggW, 256, 0,
        esf, (long)PD, aggW + 128, 256, 0,
        aggB, 0, pop,
        xatt_a, (long)ND, PP);

    // 5) agg[a] = seg-mean of xi over dst (graphs 0-2)
    gather_mean<<<dim3(nB, AA), 256>>>(xi, 0, 0, agg, (long)ND);

    // 6) x_att_b = agg @ W_l1^T + b_l1 + x_att_a @ W_r1^T
    gemm_tc<true, false, false, true><<<dim3(gN, AA), 512, GEMM_SMEM>>>(
        agg, DD, (long)ND, wl1, 128, 16384,
        xatt_a, (long)ND, wr1, 128, 16384,
        bl1, DD, nullptr,
        xatt_b, (long)ND, NN);

    // 7) population rows: x_att_b[pop] = relu(x_att_b[pop] @ (inv(proj)+I))
    gemm_tc<false, true, true, false><<<dim3(gP, AA), 512, GEMM_SMEM>>>(
        xatt_b, DD, (long)ND, MT, 128, 16384,
        nullptr, 0, nullptr, 0, 0, nullptr, 0, pop,
        xatt_b, (long)ND, PP);

    // 8) agg[a] = seg-mean of x_att_b over src (graphs 3-5)
    gather_mean<<<dim3(nB, AA), 256>>>(xatt_b, (long)ND, 3, agg, (long)ND);

    // 9) x_att_out = agg @ W_l2^T + b_l2 + x_att_b @ W_r2^T  -> d_out[N*D:]
    gemm_tc<true, false, false, true><<<dim3(gN, AA), 512, GEMM_SMEM>>>(
        agg, DD, (long)ND, wl2, 128, 16384,
        xatt_b, (long)ND, wr2, 128, 16384,
        bl2, DD, nullptr,
        out + ND, (long)ND, NN);

    // 10) agg3 = family seg-mean of xi (graph 6)
    gather_mean<<<dim3(nB, 1), 256>>>(xi, 0, 6, agg3, 0);

    // 11) x_ind_out = agg3 @ W_l3^T + b_l3 + xi @ W_r3^T -> d_out[0:]
    gemm_tc<true, false, false, true><<<dim3(gN, 1), 512, GEMM_SMEM>>>(
        agg3, DD, 0, wl3, 128, 0,
        xi, 0, wr3, 128, 0,
        bl3, 0, nullptr,
        out, 0, NN);
}

// round 6
// speedup vs baseline: 1.5648x; 1.0538x over previous
#include <cuda_runtime.h>
#include <cuda_bf16.h>
#include <cstdint>
#include <cstddef>

#define NN 100000
#define DD 128
#define AA 3
#define PP 50000
#define EE 500000
#define EFN 500000

#define ND  ((size_t)NN * DD)
#define AND ((size_t)AA * NN * DD)
#define PD  ((size_t)PP * DD)

// ---------------- scratch (static device globals; no allocation) ----------------
__device__ float  g_xatt_a[AA * NN * DD];
__device__ float  g_xatt_b[AA * NN * DD];
__device__ float  g_agg   [AA * NN * DD];
__device__ float  g_agg3  [NN * DD];
__device__ float  g_esf   [AA * PP * DD];
__device__ float  g_projT [AA * 128 * 128];  // proj^T: [o][i]
__device__ double g_inv   [AA * 128 * 256];  // Gauss-Jordan scratch
__device__ float  g_MT    [AA * 128 * 128];  // (inv(proj)+I)^T: [o][i]
// CSR structures for the 7 edge graphs (0-2: attr dst-seg, 3-5: attr src-seg, 6: family)
__device__ int    g_rowptr[7 * (NN + 1)];
__device__ int    g_fill  [7 * NN];
__device__ int    g_eord  [7 * EE];

// m16n8k16 bf16 mma (sm_80+ portable)
__device__ __forceinline__ void mma16(float* c, const uint32_t* a, uint32_t b0, uint32_t b1) {
    asm volatile("mma.sync.aligned.m16n8k16.row.col.f32.bf16.bf16.f32 "
                 "{%0,%1,%2,%3}, {%4,%5,%6,%7}, {%8,%9}, {%0,%1,%2,%3};"
                 : "+f"(c[0]), "+f"(c[1]), "+f"(c[2]), "+f"(c[3])
                 : "r"(a[0]), "r"(a[1]), "r"(a[2]), "r"(a[3]), "r"(b0), "r"(b1));
}
// split (x,y) into packed bf16x2 hi + lo (x in low half, y in high half)
__device__ __forceinline__ uint32_t packsplit(float x, float y, uint32_t& lopack) {
    float hx = __bfloat162float(__float2bfloat16(x));
    float hy = __bfloat162float(__float2bfloat16(y));
    uint32_t hi;
    asm("cvt.rn.bf16x2.f32 %0, %1, %2;" : "=r"(hi) : "f"(hy), "f"(hx));
    asm("cvt.rn.bf16x2.f32 %0, %1, %2;" : "=r"(lopack) : "f"(y - hy), "f"(x - hx));
    return hi;
}

// ---------------- weight transpose: dst[b][o][i] = src[b][i][o] -----------------
__global__ void transpose_wt(float* __restrict__ dst, const float* __restrict__ src) {
    int b = blockIdx.x;
    const float* s = src + (size_t)b * 16384;
    float* d = dst + (size_t)b * 16384;
    for (int idx = threadIdx.x; idx < 16384; idx += blockDim.x) {
        int o = idx >> 7, i = idx & 127;
        d[idx] = s[(size_t)i * 128 + o];
    }
}

// ---------------- fp64 Gauss-Jordan (1024 thr, smem pivot row) ------------------
__global__ __launch_bounds__(1024)
void inv_kernel(const float* __restrict__ proj) {
    int a = blockIdx.x;
    double* A = g_inv + (size_t)a * 128 * 256;
    int tid = threadIdx.x;

    for (int idx = tid; idx < 128 * 256; idx += 1024) {
        int r = idx >> 8, c = idx & 255;
        A[idx] = (c < 128) ? (double)proj[(size_t)a * 16384 + r * 128 + c]
                           : ((c - 128) == r ? 1.0 : 0.0);
    }
    __syncthreads();

    __shared__ double sP[256];
    __shared__ double pv[128];
    __shared__ int    pi[128];
    for (int k = 0; k < 128; k++) {
        if (tid < 128) {
            pv[tid] = (tid >= k) ? fabs(A[(size_t)tid * 256 + k]) : -1.0;
            pi[tid] = tid;
        }
        __syncthreads();
        for (int s = 64; s > 0; s >>= 1) {
            if (tid < s && pv[tid + s] > pv[tid]) { pv[tid] = pv[tid + s]; pi[tid] = pi[tid + s]; }
            __syncthreads();
        }
        int piv = pi[0];
        if (tid < 256) {
            double pvv = A[(size_t)piv * 256 + k];     // broadcast
            double pk  = A[(size_t)piv * 256 + tid];
            double ak  = A[(size_t)k   * 256 + tid];
            double np  = pk / pvv;
            sP[tid] = np;
            A[(size_t)k * 256 + tid] = np;
            if (piv != k) A[(size_t)piv * 256 + tid] = ak;
        }
        __syncthreads();
        int r = tid >> 3, h = tid & 7;
        double f = (r != k) ? A[(size_t)r * 256 + k] : 0.0;
        __syncthreads();
        if (r != k) {
            int j0 = h * 32;
            #pragma unroll 8
            for (int j = j0; j < j0 + 32; j++)
                A[(size_t)r * 256 + j] -= f * sP[j];
        }
        __syncthreads();
    }
    for (int idx = tid; idx < 16384; idx += 1024) {
        int o = idx >> 7, i = idx & 127;
        g_MT[(size_t)a * 16384 + idx] =
            (float)(A[(size_t)i * 256 + 128 + o] + (i == o ? 1.0 : 0.0));
    }
}

// ---------------- CSR build ------------------------------------------------------
__device__ __forceinline__ void graph_ptrs(int g, const int* eia, const int* eif,
                                           const int** gi, const int** si) {
    if (g < 3)      { *gi = eia + (size_t)g * 2 * EE;            *si = eia + (size_t)g * 2 * EE + EE; }
    else if (g < 6) { *gi = eia + (size_t)(g - 3) * 2 * EE + EE; *si = eia + (size_t)(g - 3) * 2 * EE; }
    else            { *gi = eif + EFN;                           *si = eif; }
}

__global__ void hist_k(const int* __restrict__ eia, const int* __restrict__ eif) {
    int g = blockIdx.y;
    const int *gi, *si;
    graph_ptrs(g, eia, eif, &gi, &si);
    int e = blockIdx.x * blockDim.x + threadIdx.x;
    if (e < EE) atomicAdd(g_fill + (size_t)g * NN + si[e], 1);
}

__global__ __launch_bounds__(1024)
void scan_k() {
    int g = blockIdx.x;
    int* cnt = g_fill + (size_t)g * NN;
    int* rp  = g_rowptr + (size_t)g * (NN + 1);
    __shared__ int partial[1024];
    int tid = threadIdx.x;
    const int chunk = (NN + 1023) / 1024;
    int s = tid * chunk, e = s + chunk; if (e > NN) e = NN; if (s > NN) s = NN;
    int sum = 0;
    for (int i = s; i < e; i++) sum += cnt[i];
    partial[tid] = sum;
    __syncthreads();
    for (int off = 1; off < 1024; off <<= 1) {
        int v = (tid >= off) ? partial[tid - off] : 0;
        __syncthreads();
        partial[tid] += v;
        __syncthreads();
    }
    int base = (tid == 0) ? 0 : partial[tid - 1];
    for (int i = s; i < e; i++) {
        int c = cnt[i];
        rp[i] = base;
        cnt[i] = base;
        base += c;
    }
    if (tid == 1023) rp[NN] = base;
}

__global__ void fill_k(const int* __restrict__ eia, const int* __restrict__ eif) {
    int g = blockIdx.y;
    const int *gi, *si;
    graph_ptrs(g, eia, eif, &gi, &si);
    int e = blockIdx.x * blockDim.x + threadIdx.x;
    if (e < EE) {
        int pos = atomicAdd(g_fill + (size_t)g * NN + si[e], 1);
        g_eord[(size_t)g * EE + pos] = gi[e];
    }
}

// ---------------- gather-mean ----------------------------------------------------
__global__ __launch_bounds__(256)
void gather_mean(const float* __restrict__ data, long dataBStr,
                 int gbase, float* __restrict__ outp, long outBStr) {
    int a = blockIdx.y;
    int g = gbase + a;
    const float* d = data + (size_t)a * dataBStr;
    float* o = outp + (size_t)a * outBStr;
    const int* rp = g_rowptr + (size_t)g * (NN + 1);
    const int* eo = g_eord + (size_t)g * EE;

    int node = blockIdx.x * 8 + (threadIdx.x >> 5);
    int lane = threadIdx.x & 31;
    if (node >= NN) return;
    int s = rp[node], e = rp[node + 1];
    float4 acc = make_float4(0.f, 0.f, 0.f, 0.f);
    int j = s;
    for (; j + 1 < e; j += 2) {
        int g0 = eo[j], g1 = eo[j + 1];
        float4 v0 = ((const float4*)(d + (size_t)g0 * DD))[lane];
        float4 v1 = ((const float4*)(d + (size_t)g1 * DD))[lane];
        acc.x += v0.x + v1.x; acc.y += v0.y + v1.y;
        acc.z += v0.z + v1.z; acc.w += v0.w + v1.w;
    }
    if (j < e) {
        float4 v = ((const float4*)(d + (size_t)eo[j] * DD))[lane];
        acc.x += v.x; acc.y += v.y; acc.z += v.z; acc.w += v.w;
    }
    float inv = 1.0f / fmaxf((float)(e - s), 1.0f);
    acc.x *= inv; acc.y *= inv; acc.z *= inv; acc.w *= inv;
    ((float4*)(o + (size_t)node * DD))[lane] = acc;
}

// ---------------- bf16 m16n8k16 fused GEMM (3-term split) ------------------------
// Out[row] = act( In1[row] @ W1^T + In2[row] @ W2^T + bias ), rows gathered if GATHER.
// Per phase: 32 k-values; smem word layout: row stride 20 words (16 data + 4 pad),
// word w holds bf16 pair (k=2w, 2w+1). Frag loads conflict-free (20g+tg distinct).
#define RSTR 20
static constexpr int GEMM_SMEM = 1024 + 4 * (128 * RSTR * 4);  // 41984

template<bool HAS2, bool GATHER, bool RELU, bool HASBIAS>
__global__ __launch_bounds__(512, 2)
void gemm_tc(const float* __restrict__ In1, int in1Stride, long in1BStr,
             const float* __restrict__ W1, int w1Stride, long w1BStr,
             const float* __restrict__ In2, long in2BStr,
             const float* __restrict__ W2, int w2Stride, long w2BStr,
             const float* __restrict__ bias, long biasBStr,
             const int*   __restrict__ ridx,
             float* __restrict__ Out, long outBStr, int nrows) {
    extern __shared__ __align__(16) char smem[];
    int*      sRow  = (int*)smem;               // 128 ints
    float*    sBias = (float*)(smem + 512);     // 128 floats
    uint32_t* sAhi = (uint32_t*)(smem + 1024);
    uint32_t* sAlo = sAhi + 128 * RSTR;
    uint32_t* sBhi = sAlo + 128 * RSTR;
    uint32_t* sBlo = sBhi + 128 * RSTR;

    {
        long a = blockIdx.y;
        In1 += a * in1BStr; W1 += a * w1BStr;
        if (HAS2) { In2 += a * in2BStr; W2 += a * w2BStr; }
        if (HASBIAS) bias += a * biasBStr;
        Out += a * outBStr;
    }

    int tid = threadIdx.x, wid = tid >> 5, lane = tid & 31;
    int g = lane >> 2, tg = lane & 3;
    int warpM = wid >> 2, warpN = wid & 3;
    int row0 = blockIdx.x * 128;

    if (tid < 128) {
        int gr = row0 + tid;
        int e = 0;
        if (gr < nrows) e = GATHER ? ridx[gr] : gr;
        sRow[tid] = e;
        if (HASBIAS) sBias[tid] = bias[tid];
    }
    __syncthreads();

    float acc[2][4][4];
    #pragma unroll
    for (int mt = 0; mt < 2; mt++)
        #pragma unroll
        for (int nt = 0; nt < 4; nt++)
            #pragma unroll
            for (int i = 0; i < 4; i++) acc[mt][nt][i] = 0.0f;

    const int np = HAS2 ? 8 : 4;
    int frr = tid >> 2, fsg = (tid & 3) * 2;  // fill: row 0..127, seg pair base (0,2,4,6)

    for (int p = 0; p < np; p++) {
        int op = HAS2 ? (p >> 2) : 0;
        int kc = (p & 3) * 32;
        // ---- fill A and B (128 rows x 32 k each), bf16 hi/lo ----
        #pragma unroll
        for (int q = 0; q < 2; q++) {
            int seg = fsg + q;                 // 0..7, float4 = k seg*4..seg*4+3
            const float* asrc;
            if (op == 0) asrc = In1 + (size_t)sRow[frr] * in1Stride + kc + seg * 4;
            else {
                int g2 = row0 + frr; if (g2 >= nrows) g2 = nrows - 1;
                asrc = In2 + (size_t)g2 * 128 + kc + seg * 4;
            }
            float4 v = *(const float4*)asrc;
            uint32_t lo0, lo1;
            uint32_t hi0 = packsplit(v.x, v.y, lo0);
            uint32_t hi1 = packsplit(v.z, v.w, lo1);
            int wa = frr * RSTR + seg * 2;
            sAhi[wa] = hi0; sAhi[wa + 1] = hi1;
            sAlo[wa] = lo0; sAlo[wa + 1] = lo1;

            const float* bw = (op == 0) ? W1 : W2;
            int bst = (op == 0) ? w1Stride : w2Stride;
            float4 w = *(const float4*)(bw + (size_t)frr * bst + kc + seg * 4);
            uint32_t wl0, wl1;
            uint32_t wh0 = packsplit(w.x, w.y, wl0);
            uint32_t wh1 = packsplit(w.z, w.w, wl1);
            sBhi[wa] = wh0; sBhi[wa + 1] = wh1;
            sBlo[wa] = wl0; sBlo[wa + 1] = wl1;
        }
        __syncthreads();

        // ---- compute: 2 k16-steps ----
        #pragma unroll
        for (int ks = 0; ks < 2; ks++) {
            int wb = ks * 8 + tg;
            uint32_t aH[2][4], aL[2][4];
            #pragma unroll
            for (int mt = 0; mt < 2; mt++) {
                int rb = (warpM * 32 + mt * 16 + g) * RSTR;
                aH[mt][0] = sAhi[rb + wb];
                aH[mt][1] = sAhi[rb + 8 * RSTR + wb];
                aH[mt][2] = sAhi[rb + wb + 4];
                aH[mt][3] = sAhi[rb + 8 * RSTR + wb + 4];
                aL[mt][0] = sAlo[rb + wb];
                aL[mt][1] = sAlo[rb + 8 * RSTR + wb];
                aL[mt][2] = sAlo[rb + wb + 4];
                aL[mt][3] = sAlo[rb + 8 * RSTR + wb + 4];
            }
            #pragma unroll
            for (int nt = 0; nt < 4; nt++) {
                int nb = (warpN * 32 + nt * 8 + g) * RSTR;
                uint32_t bh0 = sBhi[nb + wb], bh1 = sBhi[nb + wb + 4];
                uint32_t bl0 = sBlo[nb + wb], bl1 = sBlo[nb + wb + 4];
                #pragma unroll
                for (int mt = 0; mt < 2; mt++) {
                    mma16(acc[mt][nt], aH[mt], bh0, bh1);
                    mma16(acc[mt][nt], aL[mt], bh0, bh1);
                    mma16(acc[mt][nt], aH[mt], bl0, bl1);
                }
            }
        }
        __syncthreads();
    }

    // ---- epilogue ----
    #pragma unroll
    for (int mt = 0; mt < 2; mt++) {
        #pragma unroll
        for (int half = 0; half < 2; half++) {
            int lr = warpM * 32 + mt * 16 + g + half * 8;
            int grow = row0 + lr;
            if (grow < nrows) {
                int orow = GATHER ? sRow[lr] : grow;
                float* ob = Out + (size_t)orow * 128;
                #pragma unroll
                for (int nt = 0; nt < 4; nt++) {
                    int col = warpN * 32 + nt * 8 + tg * 2;
                    float v0 = acc[mt][nt][half * 2 + 0];
                    float v1 = acc[mt][nt][half * 2 + 1];
                    if (HASBIAS) { v0 += sBias[col]; v1 += sBias[col + 1]; }
                    if (RELU) { v0 = fmaxf(v0, 0.0f); v1 = fmaxf(v1, 0.0f); }
                    float2 pp; pp.x = v0; pp.y = v1;
                    *(float2*)(ob + col) = pp;
                }
            }
        }
    }
}

// ---------------- host orchestration -------------------------------------------
extern "C" void kernel_launch(void* const* d_in, const int* in_sizes, int n_in,
                              void* d_out, int out_size) {
    int iXI, iXA, iPF, iPOP, iEIA, iEIF, iPROJ, iAGGW, iAGGB,
        iWL1, iBL1, iWR1, iWL2, iBL2, iWR2, iWL3, iBL3, iWR3;
    if (in_sizes[3] == PP) {  // setup_inputs dict order
        iXI = 0; iXA = 1; iPF = 2; iPOP = 3; iEIA = 4; iEIF = 5;
        iPROJ = 6; iAGGW = 7; iAGGB = 8; iWL1 = 9; iBL1 = 10; iWR1 = 11;
        iWL2 = 12; iBL2 = 13; iWR2 = 14; iWL3 = 15; iBL3 = 16; iWR3 = 17;
    } else {                  // reference() signature order
        iXI = 0; iXA = 1; iPF = 2; iPROJ = 3; iAGGW = 4; iAGGB = 5;
        iWL1 = 6; iBL1 = 7; iWR1 = 8; iWL2 = 9; iBL2 = 10; iWR2 = 11;
        iWL3 = 12; iBL3 = 13; iWR3 = 14; iPOP = 15; iEIA = 16; iEIF = 17;
    }

    const float* xi   = (const float*)d_in[iXI];
    const float* xa   = (const float*)d_in[iXA];
    const float* pf   = (const float*)d_in[iPF];
    const int*   pop  = (const int*)d_in[iPOP];
    const int*   eia  = (const int*)d_in[iEIA];
    const int*   eif  = (const int*)d_in[iEIF];
    const float* proj = (const float*)d_in[iPROJ];
    const float* aggW = (const float*)d_in[iAGGW];
    const float* aggB = (const float*)d_in[iAGGB];
    const float* wl1  = (const float*)d_in[iWL1];
    const float* bl1  = (const float*)d_in[iBL1];
    const float* wr1  = (const float*)d_in[iWR1];
    const float* wl2  = (const float*)d_in[iWL2];
    const float* bl2  = (const float*)d_in[iBL2];
    const float* wr2  = (const float*)d_in[iWR2];
    const float* wl3  = (const float*)d_in[iWL3];
    const float* bl3  = (const float*)d_in[iBL3];
    const float* wr3  = (const float*)d_in[iWR3];

    float* out = (float*)d_out;  // [x_ind_out (N*D)] then [x_att_out (A*N*D)]

    float *xatt_a, *xatt_b, *agg, *agg3, *esf, *projT, *MT;
    int *fillp;
    cudaGetSymbolAddress((void**)&xatt_a, g_xatt_a);
    cudaGetSymbolAddress((void**)&xatt_b, g_xatt_b);
    cudaGetSymbolAddress((void**)&agg,    g_agg);
    cudaGetSymbolAddress((void**)&agg3,   g_agg3);
    cudaGetSymbolAddress((void**)&esf,    g_esf);
    cudaGetSymbolAddress((void**)&projT,  g_projT);
    cudaGetSymbolAddress((void**)&MT,     g_MT);
    cudaGetSymbolAddress((void**)&fillp,  g_fill);

    cudaFuncSetAttribute(gemm_tc<false, false, false, false>,
                         cudaFuncAttributeMaxDynamicSharedMemorySize, GEMM_SMEM);
    cudaFuncSetAttribute(gemm_tc<true, true, true, true>,
                         cudaFuncAttributeMaxDynamicSharedMemorySize, GEMM_SMEM);
    cudaFuncSetAttribute(gemm_tc<true, false, false, true>,
                         cudaFuncAttributeMaxDynamicSharedMemorySize, GEMM_SMEM);
    cudaFuncSetAttribute(gemm_tc<false, true, true, false>,
                         cudaFuncAttributeMaxDynamicSharedMemorySize, GEMM_SMEM);

    const int gP = (PP + 127) / 128;  // 391
    const int gN = (NN + 127) / 128;  // 782
    const int eB = (EE + 255) / 256;
    const int nB = (NN + 7) / 8;

    // --- prep: transposes + inverse ---
    transpose_wt<<<AA, 256>>>(projT, proj);
    inv_kernel<<<AA, 1024>>>(proj);

    // --- CSR build for all 7 graphs ---
    cudaMemsetAsync(fillp, 0, (size_t)7 * NN * sizeof(int), 0);
    hist_k<<<dim3(eB, 7), 256>>>(eia, eif);
    scan_k<<<7, 1024>>>();
    fill_k<<<dim3(eB, 7), 256>>>(eia, eif);

    // 3) esf[a] = PF[:,a,:] @ proj[a]
    gemm_tc<false, false, false, false><<<dim3(gP, AA), 512, GEMM_SMEM>>>(
        pf, AA * DD, DD, projT, 128, 16384,
        nullptr, 0, nullptr, 0, 0, nullptr, 0, nullptr,
        esf, (long)PD, PP);

    // 4) x_att_a = copy(xa); population rows = relu([xa[pop], esf] @ aggW^T + b)
    cudaMemcpyAsync(xatt_a, xa, AND * sizeof(float), cudaMemcpyDeviceToDevice, 0);
    gemm_tc<true, true, true, true><<<dim3(gP, AA), 512, GEMM_SMEM>>>(
        xa, DD, (long)ND, aggW, 256, 0,
        esf, (long)PD, aggW + 128, 256, 0,
        aggB, 0, pop,
        xatt_a, (long)ND, PP);

    // 5) agg[a] = seg-mean of xi over dst (graphs 0-2)
    gather_mean<<<dim3(nB, AA), 256>>>(xi, 0, 0, agg, (long)ND);

    // 6) x_att_b = agg @ W_l1^T + b_l1 + x_att_a @ W_r1^T
    gemm_tc<true, false, false, true><<<dim3(gN, AA), 512, GEMM_SMEM>>>(
        agg, DD, (long)ND, wl1, 128, 16384,
        xatt_a, (long)ND, wr1, 128, 16384,
        bl1, DD, nullptr,
        xatt_b, (long)ND, NN);

    // 7) population rows: x_att_b[pop] = relu(x_att_b[pop] @ (inv(proj)+I))
    gemm_tc<false, true, true, false><<<dim3(gP, AA), 512, GEMM_SMEM>>>(
        xatt_b, DD, (long)ND, MT, 128, 16384,
        nullptr, 0, nullptr, 0, 0, nullptr, 0, pop,
        xatt_b, (long)ND, PP);

    // 8) agg[a] = seg-mean of x_att_b over src (graphs 3-5)
    gather_mean<<<dim3(nB, AA), 256>>>(xatt_b, (long)ND, 3, agg, (long)ND);

    // 9) x_att_out = agg @ W_l2^T + b_l2 + x_att_b @ W_r2^T  -> d_out[N*D:]
    gemm_tc<true, false, false, true><<<dim3(gN, AA), 512, GEMM_SMEM>>>(
        agg, DD, (long)ND, wl2, 128, 16384,
        xatt_b, (long)ND, wr2, 128, 16384,
        bl2, DD, nullptr,
        out + ND, (long)ND, NN);

    // 10) agg3 = family seg-mean of xi (graph 6)
    gather_mean<<<dim3(nB, 1), 256>>>(xi, 0, 6, agg3, 0);

    // 11) x_ind_out = agg3 @ W_l3^T + b_l3 + xi @ W_r3^T -> d_out[0:]
    gemm_tc<true, false, false, true><<<dim3(gN, 1), 512, GEMM_SMEM>>>(
        agg3, DD, 0, wl3, 128, 0,
        xi, 0, wr3, 128, 0,
        bl3, 0, nullptr,
        out, 0, NN);
}

// round 7
// speedup vs baseline: 1.5666x; 1.0011x over previous
#include <cuda_runtime.h>
#include <cuda_bf16.h>
#include <cstdint>
#include <cstddef>

#define NN 100000
#define DD 128
#define AA 3
#define PP 50000
#define EE 500000
#define EFN 500000

#define ND  ((size_t)NN * DD)
#define AND ((size_t)AA * NN * DD)
#define PD  ((size_t)PP * DD)

// ---------------- scratch (static device globals; no allocation) ----------------
__device__ float  g_xatt_a[AA * NN * DD];
__device__ float  g_xatt_b[AA * NN * DD];
__device__ float  g_agg   [AA * NN * DD];
__device__ float  g_agg3  [NN * DD];
__device__ float  g_esf   [AA * PP * DD];
__device__ float  g_projT [AA * 128 * 128];  // proj^T: [o][i]
__device__ double g_inv   [AA * 128 * 256];  // Gauss-Jordan scratch
__device__ float  g_MT    [AA * 128 * 128];  // (inv(proj)+I)^T: [o][i]
// CSR structures for the 7 edge graphs (0-2: attr dst-seg, 3-5: attr src-seg, 6: family)
__device__ int    g_rowptr[7 * (NN + 1)];
__device__ int    g_fill  [7 * NN];
__device__ int    g_eord  [7 * EE];

// m16n8k16 bf16 mma (sm_80+ portable)
__device__ __forceinline__ void mma16(float* c, const uint32_t* a, uint32_t b0, uint32_t b1) {
    asm volatile("mma.sync.aligned.m16n8k16.row.col.f32.bf16.bf16.f32 "
                 "{%0,%1,%2,%3}, {%4,%5,%6,%7}, {%8,%9}, {%0,%1,%2,%3};"
                 : "+f"(c[0]), "+f"(c[1]), "+f"(c[2]), "+f"(c[3])
                 : "r"(a[0]), "r"(a[1]), "r"(a[2]), "r"(a[3]), "r"(b0), "r"(b1));
}
// split (x,y) into packed bf16x2 hi + lo (x in low half, y in high half)
__device__ __forceinline__ uint32_t packsplit(float x, float y, uint32_t& lopack) {
    float hx = __bfloat162float(__float2bfloat16(x));
    float hy = __bfloat162float(__float2bfloat16(y));
    uint32_t hi;
    asm("cvt.rn.bf16x2.f32 %0, %1, %2;" : "=r"(hi) : "f"(hy), "f"(hx));
    asm("cvt.rn.bf16x2.f32 %0, %1, %2;" : "=r"(lopack) : "f"(y - hy), "f"(x - hx));
    return hi;
}

// ---------------- weight transpose: dst[b][o][i] = src[b][i][o] -----------------
__global__ void transpose_wt(float* __restrict__ dst, const float* __restrict__ src) {
    int b = blockIdx.x;
    const float* s = src + (size_t)b * 16384;
    float* d = dst + (size_t)b * 16384;
    for (int idx = threadIdx.x; idx < 16384; idx += blockDim.x) {
        int o = idx >> 7, i = idx & 127;
        d[idx] = s[(size_t)i * 128 + o];
    }
}

// ---------------- fp64 Gauss-Jordan (1024 thr, smem pivot row) ------------------
__global__ __launch_bounds__(1024)
void inv_kernel(const float* __restrict__ proj) {
    int a = blockIdx.x;
    double* A = g_inv + (size_t)a * 128 * 256;
    int tid = threadIdx.x;

    for (int idx = tid; idx < 128 * 256; idx += 1024) {
        int r = idx >> 8, c = idx & 255;
        A[idx] = (c < 128) ? (double)proj[(size_t)a * 16384 + r * 128 + c]
                           : ((c - 128) == r ? 1.0 : 0.0);
    }
    __syncthreads();

    __shared__ double sP[256];
    __shared__ double pv[128];
    __shared__ int    pi[128];
    for (int k = 0; k < 128; k++) {
        if (tid < 128) {
            pv[tid] = (tid >= k) ? fabs(A[(size_t)tid * 256 + k]) : -1.0;
            pi[tid] = tid;
        }
        __syncthreads();
        for (int s = 64; s > 0; s >>= 1) {
            if (tid < s && pv[tid + s] > pv[tid]) { pv[tid] = pv[tid + s]; pi[tid] = pi[tid + s]; }
            __syncthreads();
        }
        int piv = pi[0];
        if (tid < 256) {
            double pvv = A[(size_t)piv * 256 + k];     // broadcast
            double pk  = A[(size_t)piv * 256 + tid];
            double ak  = A[(size_t)k   * 256 + tid];
            double np  = pk / pvv;
            sP[tid] = np;
            A[(size_t)k * 256 + tid] = np;
            if (piv != k) A[(size_t)piv * 256 + tid] = ak;
        }
        __syncthreads();
        int r = tid >> 3, h = tid & 7;
        double f = (r != k) ? A[(size_t)r * 256 + k] : 0.0;
        __syncthreads();
        if (r != k) {
            int j0 = h * 32;
            #pragma unroll 8
            for (int j = j0; j < j0 + 32; j++)
                A[(size_t)r * 256 + j] -= f * sP[j];
        }
        __syncthreads();
    }
    for (int idx = tid; idx < 16384; idx += 1024) {
        int o = idx >> 7, i = idx & 127;
        g_MT[(size_t)a * 16384 + idx] =
            (float)(A[(size_t)i * 256 + 128 + o] + (i == o ? 1.0 : 0.0));
    }
}

// ---------------- CSR build ------------------------------------------------------
__device__ __forceinline__ void graph_ptrs(int g, const int* eia, const int* eif,
                                           const int** gi, const int** si) {
    if (g < 3)      { *gi = eia + (size_t)g * 2 * EE;            *si = eia + (size_t)g * 2 * EE + EE; }
    else if (g < 6) { *gi = eia + (size_t)(g - 3) * 2 * EE + EE; *si = eia + (size_t)(g - 3) * 2 * EE; }
    else            { *gi = eif + EFN;                           *si = eif; }
}

__global__ void hist_k(const int* __restrict__ eia, const int* __restrict__ eif) {
    int g = blockIdx.y;
    const int *gi, *si;
    graph_ptrs(g, eia, eif, &gi, &si);
    int e = blockIdx.x * blockDim.x + threadIdx.x;
    if (e < EE) atomicAdd(g_fill + (size_t)g * NN + si[e], 1);
}

__global__ __launch_bounds__(1024)
void scan_k() {
    int g = blockIdx.x;
    int* cnt = g_fill + (size_t)g * NN;
    int* rp  = g_rowptr + (size_t)g * (NN + 1);
    __shared__ int partial[1024];
    int tid = threadIdx.x;
    const int chunk = (NN + 1023) / 1024;
    int s = tid * chunk, e = s + chunk; if (e > NN) e = NN; if (s > NN) s = NN;
    int sum = 0;
    for (int i = s; i < e; i++) sum += cnt[i];
    partial[tid] = sum;
    __syncthreads();
    for (int off = 1; off < 1024; off <<= 1) {
        int v = (tid >= off) ? partial[tid - off] : 0;
        __syncthreads();
        partial[tid] += v;
        __syncthreads();
    }
    int base = (tid == 0) ? 0 : partial[tid - 1];
    for (int i = s; i < e; i++) {
        int c = cnt[i];
        rp[i] = base;
        cnt[i] = base;
        base += c;
    }
    if (tid == 1023) rp[NN] = base;
}

__global__ void fill_k(const int* __restrict__ eia, const int* __restrict__ eif) {
    int g = blockIdx.y;
    const int *gi, *si;
    graph_ptrs(g, eia, eif, &gi, &si);
    int e = blockIdx.x * blockDim.x + threadIdx.x;
    if (e < EE) {
        int pos = atomicAdd(g_fill + (size_t)g * NN + si[e], 1);
        g_eord[(size_t)g * EE + pos] = gi[e];
    }
}

// ---------------- gather-mean ----------------------------------------------------
__global__ __launch_bounds__(256)
void gather_mean(const float* __restrict__ data, long dataBStr,
                 int gbase, float* __restrict__ outp, long outBStr) {
    int a = blockIdx.y;
    int g = gbase + a;
    const float* d = data + (size_t)a * dataBStr;
    float* o = outp + (size_t)a * outBStr;
    const int* rp = g_rowptr + (size_t)g * (NN + 1);
    const int* eo = g_eord + (size_t)g * EE;

    int node = blockIdx.x * 8 + (threadIdx.x >> 5);
    int lane = threadIdx.x & 31;
    if (node >= NN) return;
    int s = rp[node], e = rp[node + 1];
    float4 acc = make_float4(0.f, 0.f, 0.f, 0.f);
    int j = s;
    for (; j + 1 < e; j += 2) {
        int g0 = eo[j], g1 = eo[j + 1];
        float4 v0 = ((const float4*)(d + (size_t)g0 * DD))[lane];
        float4 v1 = ((const float4*)(d + (size_t)g1 * DD))[lane];
        acc.x += v0.x + v1.x; acc.y += v0.y + v1.y;
        acc.z += v0.z + v1.z; acc.w += v0.w + v1.w;
    }
    if (j < e) {
        float4 v = ((const float4*)(d + (size_t)eo[j] * DD))[lane];
        acc.x += v.x; acc.y += v.y; acc.z += v.z; acc.w += v.w;
    }
    float inv = 1.0f / fmaxf((float)(e - s), 1.0f);
    acc.x *= inv; acc.y *= inv; acc.z *= inv; acc.w *= inv;
    ((float4*)(o + (size_t)node * DD))[lane] = acc;
}

// ---------------- bf16 m16n8k16 fused GEMM (3-term split) ------------------------
// Out[row] = act( In1[row] @ W1^T + In2[row] @ W2^T + bias ), rows gathered if GATHER.
// Per phase: 32 k-values; smem word layout: row stride 20 words (16 data + 4 pad),
// word w holds bf16 pair (k=2w, 2w+1). Frag loads conflict-free (20g+tg distinct).
#define RSTR 20
static constexpr int GEMM_SMEM = 1024 + 4 * (128 * RSTR * 4);  // 41984

template<bool HAS2, bool GATHER, bool RELU, bool HASBIAS>
__global__ __launch_bounds__(512, 2)
void gemm_tc(const float* __restrict__ In1, int in1Stride, long in1BStr,
             const float* __restrict__ W1, int w1Stride, long w1BStr,
             const float* __restrict__ In2, long in2BStr,
             const float* __restrict__ W2, int w2Stride, long w2BStr,
             const float* __restrict__ bias, long biasBStr,
             const int*   __restrict__ ridx,
             float* __restrict__ Out, long outBStr, int nrows) {
    extern __shared__ __align__(16) char smem[];
    int*      sRow  = (int*)smem;               // 128 ints
    float*    sBias = (float*)(smem + 512);     // 128 floats
    uint32_t* sAhi = (uint32_t*)(smem + 1024);
    uint32_t* sAlo = sAhi + 128 * RSTR;
    uint32_t* sBhi = sAlo + 128 * RSTR;
    uint32_t* sBlo = sBhi + 128 * RSTR;

    {
        long a = blockIdx.y;
        In1 += a * in1BStr; W1 += a * w1BStr;
        if (HAS2) { In2 += a * in2BStr; W2 += a * w2BStr; }
        if (HASBIAS) bias += a * biasBStr;
        Out += a * outBStr;
    }

    int tid = threadIdx.x, wid = tid >> 5, lane = tid & 31;
    int g = lane >> 2, tg = lane & 3;
    int warpM = wid >> 2, warpN = wid & 3;
    int row0 = blockIdx.x * 128;

    if (tid < 128) {
        int gr = row0 + tid;
        int e = 0;
        if (gr < nrows) e = GATHER ? ridx[gr] : gr;
        sRow[tid] = e;
        if (HASBIAS) sBias[tid] = bias[tid];
    }
    __syncthreads();

    float acc[2][4][4];
    #pragma unroll
    for (int mt = 0; mt < 2; mt++)
        #pragma unroll
        for (int nt = 0; nt < 4; nt++)
            #pragma unroll
            for (int i = 0; i < 4; i++) acc[mt][nt][i] = 0.0f;

    const int np = HAS2 ? 8 : 4;
    int frr = tid >> 2, fsg = (tid & 3) * 2;  // fill: row 0..127, seg pair base (0,2,4,6)

    for (int p = 0; p < np; p++) {
        int op = HAS2 ? (p >> 2) : 0;
        int kc = (p & 3) * 32;
        // ---- fill A and B (128 rows x 32 k each), bf16 hi/lo ----
        #pragma unroll
        for (int q = 0; q < 2; q++) {
            int seg = fsg + q;                 // 0..7, float4 = k seg*4..seg*4+3
            const float* asrc;
            if (op == 0) asrc = In1 + (size_t)sRow[frr] * in1Stride + kc + seg * 4;
            else {
                int g2 = row0 + frr; if (g2 >= nrows) g2 = nrows - 1;
                asrc = In2 + (size_t)g2 * 128 + kc + seg * 4;
            }
            float4 v = *(const float4*)asrc;
            uint32_t lo0, lo1;
            uint32_t hi0 = packsplit(v.x, v.y, lo0);
            uint32_t hi1 = packsplit(v.z, v.w, lo1);
            int wa = frr * RSTR + seg * 2;
            sAhi[wa] = hi0; sAhi[wa + 1] = hi1;
            sAlo[wa] = lo0; sAlo[wa + 1] = lo1;

            const float* bw = (op == 0) ? W1 : W2;
            int bst = (op == 0) ? w1Stride : w2Stride;
            float4 w = *(const float4*)(bw + (size_t)frr * bst + kc + seg * 4);
            uint32_t wl0, wl1;
            uint32_t wh0 = packsplit(w.x, w.y, wl0);
            uint32_t wh1 = packsplit(w.z, w.w, wl1);
            sBhi[wa] = wh0; sBhi[wa + 1] = wh1;
            sBlo[wa] = wl0; sBlo[wa + 1] = wl1;
        }
        __syncthreads();

        // ---- compute: 2 k16-steps ----
        #pragma unroll
        for (int ks = 0; ks < 2; ks++) {
            int wb = ks * 8 + tg;
            uint32_t aH[2][4], aL[2][4];
            #pragma unroll
            for (int mt = 0; mt < 2; mt++) {
                int rb = (warpM * 32 + mt * 16 + g) * RSTR;
                aH[mt][0] = sAhi[rb + wb];
                aH[mt][1] = sAhi[rb + 8 * RSTR + wb];
                aH[mt][2] = sAhi[rb + wb + 4];
                aH[mt][3] = sAhi[rb + 8 * RSTR + wb + 4];
                aL[mt][0] = sAlo[rb + wb];
                aL[mt][1] = sAlo[rb + 8 * RSTR + wb];
                aL[mt][2] = sAlo[rb + wb + 4];
                aL[mt][3] = sAlo[rb + 8 * RSTR + wb + 4];
            }
            #pragma unroll
            for (int nt = 0; nt < 4; nt++) {
                int nb = (warpN * 32 + nt * 8 + g) * RSTR;
                uint32_t bh0 = sBhi[nb + wb], bh1 = sBhi[nb + wb + 4];
                uint32_t bl0 = sBlo[nb + wb], bl1 = sBlo[nb + wb + 4];
                #pragma unroll
                for (int mt = 0; mt < 2; mt++) {
                    mma16(acc[mt][nt], aH[mt], bh0, bh1);
                    mma16(acc[mt][nt], aL[mt], bh0, bh1);
                    mma16(acc[mt][nt], aH[mt], bl0, bl1);
                }
            }
        }
        __syncthreads();
    }

    // ---- epilogue ----
    #pragma unroll
    for (int mt = 0; mt < 2; mt++) {
        #pragma unroll
        for (int half = 0; half < 2; half++) {
            int lr = warpM * 32 + mt * 16 + g + half * 8;
            int grow = row0 + lr;
            if (grow < nrows) {
                int orow = GATHER ? sRow[lr] : grow;
                float* ob = Out + (size_t)orow * 128;
                #pragma unroll
                for (int nt = 0; nt < 4; nt++) {
                    int col = warpN * 32 + nt * 8 + tg * 2;
                    float v0 = acc[mt][nt][half * 2 + 0];
                    float v1 = acc[mt][nt][half * 2 + 1];
                    if (HASBIAS) { v0 += sBias[col]; v1 += sBias[col + 1]; }
                    if (RELU) { v0 = fmaxf(v0, 0.0f); v1 = fmaxf(v1, 0.0f); }
                    float2 pp; pp.x = v0; pp.y = v1;
                    *(float2*)(ob + col) = pp;
                }
            }
        }
    }
}

// ---------------- host orchestration -------------------------------------------
extern "C" void kernel_launch(void* const* d_in, const int* in_sizes, int n_in,
                              void* d_out, int out_size) {
    int iXI, iXA, iPF, iPOP, iEIA, iEIF, iPROJ, iAGGW, iAGGB,
        iWL1, iBL1, iWR1, iWL2, iBL2, iWR2, iWL3, iBL3, iWR3;
    if (in_sizes[3] == PP) {  // setup_inputs dict order
        iXI = 0; iXA = 1; iPF = 2; iPOP = 3; iEIA = 4; iEIF = 5;
        iPROJ = 6; iAGGW = 7; iAGGB = 8; iWL1 = 9; iBL1 = 10; iWR1 = 11;
        iWL2 = 12; iBL2 = 13; iWR2 = 14; iWL3 = 15; iBL3 = 16; iWR3 = 17;
    } else {                  // reference() signature order
        iXI = 0; iXA = 1; iPF = 2; iPROJ = 3; iAGGW = 4; iAGGB = 5;
        iWL1 = 6; iBL1 = 7; iWR1 = 8; iWL2 = 9; iBL2 = 10; iWR2 = 11;
        iWL3 = 12; iBL3 = 13; iWR3 = 14; iPOP = 15; iEIA = 16; iEIF = 17;
    }

    const float* xi   = (const float*)d_in[iXI];
    const float* xa   = (const float*)d_in[iXA];
    const float* pf   = (const float*)d_in[iPF];
    const int*   pop  = (const int*)d_in[iPOP];
    const int*   eia  = (const int*)d_in[iEIA];
    const int*   eif  = (const int*)d_in[iEIF];
    const float* proj = (const float*)d_in[iPROJ];
    const float* aggW = (const float*)d_in[iAGGW];
    const float* aggB = (const float*)d_in[iAGGB];
    const float* wl1  = (const float*)d_in[iWL1];
    const float* bl1  = (const float*)d_in[iBL1];
    const float* wr1  = (const float*)d_in[iWR1];
    const float* wl2  = (const float*)d_in[iWL2];
    const float* bl2  = (const float*)d_in[iBL2];
    const float* wr2  = (const float*)d_in[iWR2];
    const float* wl3  = (const float*)d_in[iWL3];
    const float* bl3  = (const float*)d_in[iBL3];
    const float* wr3  = (const float*)d_in[iWR3];

    float* out = (float*)d_out;  // [x_ind_out (N*D)] then [x_att_out (A*N*D)]

    float *xatt_a, *xatt_b, *agg, *agg3, *esf, *projT, *MT;
    int *fillp;
    cudaGetSymbolAddress((void**)&xatt_a, g_xatt_a);
    cudaGetSymbolAddress((void**)&xatt_b, g_xatt_b);
    cudaGetSymbolAddress((void**)&agg,    g_agg);
    cudaGetSymbolAddress((void**)&agg3,   g_agg3);
    cudaGetSymbolAddress((void**)&esf,    g_esf);
    cudaGetSymbolAddress((void**)&projT,  g_projT);
    cudaGetSymbolAddress((void**)&MT,     g_MT);
    cudaGetSymbolAddress((void**)&fillp,  g_fill);

    cudaFuncSetAttribute(gemm_tc<false, false, false, false>,
                         cudaFuncAttributeMaxDynamicSharedMemorySize, GEMM_SMEM);
    cudaFuncSetAttribute(gemm_tc<true, true, true, true>,
                         cudaFuncAttributeMaxDynamicSharedMemorySize, GEMM_SMEM);
    cudaFuncSetAttribute(gemm_tc<true, false, false, true>,
                         cudaFuncAttributeMaxDynamicSharedMemorySize, GEMM_SMEM);
    cudaFuncSetAttribute(gemm_tc<false, true, true, false>,
                         cudaFuncAttributeMaxDynamicSharedMemorySize, GEMM_SMEM);

    const int gP = (PP + 127) / 128;  // 391
    const int gN = (NN + 127) / 128;  // 782
    const int eB = (EE + 255) / 256;
    const int nB = (NN + 7) / 8;

    // --- prep: transposes + inverse ---
    transpose_wt<<<AA, 256>>>(projT, proj);
    inv_kernel<<<AA, 1024>>>(proj);

    // --- CSR build for all 7 graphs ---
    cudaMemsetAsync(fillp, 0, (size_t)7 * NN * sizeof(int), 0);
    hist_k<<<dim3(eB, 7), 256>>>(eia, eif);
    scan_k<<<7, 1024>>>();
    fill_k<<<dim3(eB, 7), 256>>>(eia, eif);

    // 3) esf[a] = PF[:,a,:] @ proj[a]
    gemm_tc<false, false, false, false><<<dim3(gP, AA), 512, GEMM_SMEM>>>(
        pf, AA * DD, DD, projT, 128, 16384,
        nullptr, 0, nullptr, 0, 0, nullptr, 0, nullptr,
        esf, (long)PD, PP);

    // 4) x_att_a = copy(xa); population rows = relu([xa[pop], esf] @ aggW^T + b)
    cudaMemcpyAsync(xatt_a, xa, AND * sizeof(float), cudaMemcpyDeviceToDevice, 0);
    gemm_tc<true, true, true, true><<<dim3(gP, AA), 512, GEMM_SMEM>>>(
        xa, DD, (long)ND, aggW, 256, 0,
        esf, (long)PD, aggW + 128, 256, 0,
        aggB, 0, pop,
        xatt_a, (long)ND, PP);

    // 5) agg[a] = seg-mean of xi over dst (graphs 0-2)
    gather_mean<<<dim3(nB, AA), 256>>>(xi, 0, 0, agg, (long)ND);

    // 6) x_att_b = agg @ W_l1^T + b_l1 + x_att_a @ W_r1^T
    gemm_tc<true, false, false, true><<<dim3(gN, AA), 512, GEMM_SMEM>>>(
        agg, DD, (long)ND, wl1, 128, 16384,
        xatt_a, (long)ND, wr1, 128, 16384,
        bl1, DD, nullptr,
        xatt_b, (long)ND, NN);

    // 7) population rows: x_att_b[pop] = relu(x_att_b[pop] @ (inv(proj)+I))
    gemm_tc<false, true, true, false><<<dim3(gP, AA), 512, GEMM_SMEM>>>(
        xatt_b, DD, (long)ND, MT, 128, 16384,
        nullptr, 0, nullptr, 0, 0, nullptr, 0, pop,
        xatt_b, (long)ND, PP);

    // 8) agg[a] = seg-mean of x_att_b over src (graphs 3-5)
    gather_mean<<<dim3(nB, AA), 256>>>(xatt_b, (long)ND, 3, agg, (long)ND);

    // 9) x_att_out = agg @ W_l2^T + b_l2 + x_att_b @ W_r2^T  -> d_out[N*D:]
    gemm_tc<true, false, false, true><<<dim3(gN, AA), 512, GEMM_SMEM>>>(
        agg, DD, (long)ND, wl2, 128, 16384,
        xatt_b, (long)ND, wr2, 128, 16384,
        bl2, DD, nullptr,
        out + ND, (long)ND, NN);

    // 10) agg3 = family seg-mean of xi (graph 6)
    gather_mean<<<dim3(nB, 1), 256>>>(xi, 0, 6, agg3, 0);

    // 11) x_ind_out = agg3 @ W_l3^T + b_l3 + xi @ W_r3^T -> d_out[0:]
    gemm_tc<true, false, false, true><<<dim3(gN, 1), 512, GEMM_SMEM>>>(
        agg3, DD, 0, wl3, 128, 0,
        xi, 0, wr3, 128, 0,
        bl3, 0, nullptr,
        out, 0, NN);
}

// round 8
// speedup vs baseline: 5.0904x; 3.2494x over previous
#include <cuda_runtime.h>
#include <cuda_bf16.h>
#include <cstdint>
#include <cstddef>

#define NN 100000
#define DD 128
#define AA 3
#define PP 50000
#define EE 500000
#define EFN 500000

#define ND  ((size_t)NN * DD)
#define AND ((size_t)AA * NN * DD)
#define PD  ((size_t)PP * DD)

// ---------------- scratch (static device globals; no allocation) ----------------
__device__ float  g_xatt_a[AA * NN * DD];
__device__ float  g_xatt_b[AA * NN * DD];
__device__ float  g_agg   [4 * NN * DD];     // slots 0-2: attr agg; slot 3: family agg
__device__ float  g_esf   [AA * PP * DD];
__device__ float  g_projT [AA * 128 * 128];  // proj^T: [o][i]
__device__ float  g_MT    [AA * 128 * 128];  // (inv(proj)+I)^T: [o][i]
// CSR structures for the 7 edge graphs (0-2: attr dst-seg, 3-5: attr src-seg, 6: family)
__device__ int    g_rowptr[7 * (NN + 1)];
__device__ int    g_fill  [7 * NN];
__device__ int    g_eord  [7 * EE];

// m16n8k16 bf16 mma (sm_80+ portable)
__device__ __forceinline__ void mma16(float* c, const uint32_t* a, uint32_t b0, uint32_t b1) {
    asm volatile("mma.sync.aligned.m16n8k16.row.col.f32.bf16.bf16.f32 "
                 "{%0,%1,%2,%3}, {%4,%5,%6,%7}, {%8,%9}, {%0,%1,%2,%3};"
                 : "+f"(c[0]), "+f"(c[1]), "+f"(c[2]), "+f"(c[3])
                 : "r"(a[0]), "r"(a[1]), "r"(a[2]), "r"(a[3]), "r"(b0), "r"(b1));
}
// split (x,y) into packed bf16x2 hi + lo (x low half, y high half)
__device__ __forceinline__ uint32_t packsplit(float x, float y, uint32_t& lopack) {
    float hx = __bfloat162float(__float2bfloat16(x));
    float hy = __bfloat162float(__float2bfloat16(y));
    uint32_t hi;
    asm("cvt.rn.bf16x2.f32 %0, %1, %2;" : "=r"(hi) : "f"(hy), "f"(hx));
    asm("cvt.rn.bf16x2.f32 %0, %1, %2;" : "=r"(lopack) : "f"(y - hy), "f"(x - hx));
    return hi;
}

// ---------------- weight transpose: dst[b][o][i] = src[b][i][o] -----------------
__global__ void transpose_wt(float* __restrict__ dst, const float* __restrict__ src) {
    int b = blockIdx.x;
    const float* s = src + (size_t)b * 16384;
    float* d = dst + (size_t)b * 16384;
    for (int idx = threadIdx.x; idx < 16384; idx += blockDim.x) {
        int o = idx >> 7, i = idx & 127;
        d[idx] = s[(size_t)i * 128 + o];
    }
}

// ---------------- fp64 in-place Gauss-Jordan inverse, all in SMEM ---------------
// S (128x128 doubles, 131072 B dynamic smem) <- inv(proj[a]); writes
// MT[o][i] = inv[i][o] + (i==o). Row pivoting; column unswap at the end.
__global__ __launch_bounds__(1024)
void inv_kernel(const float* __restrict__ proj) {
    extern __shared__ double S[];            // 128*128
    __shared__ double pv[128];
    __shared__ int    pi[128];
    __shared__ int    perm[128];

    int a = blockIdx.x;
    int tid = threadIdx.x;
    int c = tid & 127, r0 = (tid >> 7) << 4; // col owned; base row (16 rows/thread)

    for (int idx = tid; idx < 16384; idx += 1024)
        S[idx] = (double)proj[(size_t)a * 16384 + idx];
    __syncthreads();

    for (int k = 0; k < 128; k++) {
        // pivot search over rows >= k on column k
        if (tid < 128) {
            pv[tid] = (tid >= k) ? fabs(S[tid * 128 + k]) : -1.0;
            pi[tid] = tid;
        }
        __syncthreads();
        for (int s = 64; s > 0; s >>= 1) {
            if (tid < s && pv[tid + s] > pv[tid]) { pv[tid] = pv[tid + s]; pi[tid] = pi[tid + s]; }
            __syncthreads();
        }
        int piv = pi[0];
        if (tid == 0) perm[k] = piv;
        // swap rows k<->piv; stash row k (pre-normalize) into pv
        if (tid < 128) {
            double vk = S[k * 128 + tid];
            if (piv != k) {
                double vp = S[piv * 128 + tid];
                S[piv * 128 + tid] = vk;
                vk = vp;
            }
            pv[tid] = vk;
        }
        __syncthreads();
        double d = pv[k];
        // normalize row k with implicit identity column: rowk[j] = (j==k ? 1 : a_kj)/d
        if (tid < 128) {
            double nv = ((tid == k) ? 1.0 : pv[tid]) / d;
            S[k * 128 + tid] = nv;
            pv[tid] = nv;
        }
        __syncthreads();
        // elimination: thread owns column c, 16 rows r0..r0+15
        double rk = pv[c];
        double f[16];
        #pragma unroll
        for (int m = 0; m < 16; m++) {
            int r = r0 + m;
            f[m] = (r == k) ? 0.0 : S[r * 128 + k];   // broadcast within warp
        }
        __syncthreads();   // all column-k reads done before overwrite
        #pragma unroll
        for (int m = 0; m < 16; m++) {
            int r = r0 + m;
            if (r != k) {
                double v = S[r * 128 + c];
                if (c == k) v = 0.0;                  // implicit identity col update
                S[r * 128 + c] = v - f[m] * rk;
            }
        }
        __syncthreads();
    }
    // undo row pivots as column swaps, reverse order
    for (int k = 127; k >= 0; k--) {
        int p = perm[k];
        if (p != k && tid < 128) {
            double t = S[tid * 128 + k];
            S[tid * 128 + k] = S[tid * 128 + p];
            S[tid * 128 + p] = t;
        }
        __syncthreads();
    }
    // MT[o][i] = inv[i][o] + (i==o)
    for (int idx = tid; idx < 16384; idx += 1024) {
        int o = idx >> 7, i = idx & 127;
        g_MT[(size_t)a * 16384 + idx] = (float)(S[i * 128 + o] + (i == o ? 1.0 : 0.0));
    }
}

// ---------------- CSR build ------------------------------------------------------
__device__ __forceinline__ void graph_ptrs(int g, const int* eia, const int* eif,
                                           const int** gi, const int** si) {
    if (g < 3)      { *gi = eia + (size_t)g * 2 * EE;            *si = eia + (size_t)g * 2 * EE + EE; }
    else if (g < 6) { *gi = eia + (size_t)(g - 3) * 2 * EE + EE; *si = eia + (size_t)(g - 3) * 2 * EE; }
    else            { *gi = eif + EFN;                           *si = eif; }
}

__global__ void hist_k(const int* __restrict__ eia, const int* __restrict__ eif) {
    int g = blockIdx.y;
    const int *gi, *si;
    graph_ptrs(g, eia, eif, &gi, &si);
    int e = blockIdx.x * blockDim.x + threadIdx.x;
    if (e < EE) atomicAdd(g_fill + (size_t)g * NN + si[e], 1);
}

__global__ __launch_bounds__(1024)
void scan_k() {
    int g = blockIdx.x;
    int* cnt = g_fill + (size_t)g * NN;
    int* rp  = g_rowptr + (size_t)g * (NN + 1);
    __shared__ int partial[1024];
    int tid = threadIdx.x;
    const int chunk = (NN + 1023) / 1024;
    int s = tid * chunk, e = s + chunk; if (e > NN) e = NN; if (s > NN) s = NN;
    int sum = 0;
    #pragma unroll 4
    for (int i = s; i < e; i++) sum += cnt[i];
    partial[tid] = sum;
    __syncthreads();
    for (int off = 1; off < 1024; off <<= 1) {
        int v = (tid >= off) ? partial[tid - off] : 0;
        __syncthreads();
        partial[tid] += v;
        __syncthreads();
    }
    int base = (tid == 0) ? 0 : partial[tid - 1];
    for (int i = s; i < e; i++) {
        int c = cnt[i];
        rp[i] = base;
        cnt[i] = base;
        base += c;
    }
    if (tid == 1023) rp[NN] = base;
}

__global__ void fill_k(const int* __restrict__ eia, const int* __restrict__ eif) {
    int g = blockIdx.y;
    const int *gi, *si;
    graph_ptrs(g, eia, eif, &gi, &si);
    int e = blockIdx.x * blockDim.x + threadIdx.x;
    if (e < EE) {
        int pos = atomicAdd(g_fill + (size_t)g * NN + si[e], 1);
        g_eord[(size_t)g * EE + pos] = gi[e];
    }
}

// ---------------- gather-mean ----------------------------------------------------
// graph = gbase + a, except a==3 maps to graph 6 (family) when fam4 set.
__global__ __launch_bounds__(256)
void gather_mean(const float* __restrict__ data, long dataBStr,
                 int gbase, int fam4, float* __restrict__ outp, long outBStr) {
    int a = blockIdx.y;
    int g = (fam4 && a == 3) ? 6 : (gbase + a);
    const float* d = data + (size_t)a * dataBStr;
    float* o = outp + (size_t)a * outBStr;
    const int* rp = g_rowptr + (size_t)g * (NN + 1);
    const int* eo = g_eord + (size_t)g * EE;

    int node = blockIdx.x * 8 + (threadIdx.x >> 5);
    int lane = threadIdx.x & 31;
    if (node >= NN) return;
    int s = rp[node], e = rp[node + 1];
    float4 acc = make_float4(0.f, 0.f, 0.f, 0.f);
    int j = s;
    for (; j + 1 < e; j += 2) {
        int g0 = eo[j], g1 = eo[j + 1];
        float4 v0 = ((const float4*)(d + (size_t)g0 * DD))[lane];
        float4 v1 = ((const float4*)(d + (size_t)g1 * DD))[lane];
        acc.x += v0.x + v1.x; acc.y += v0.y + v1.y;
        acc.z += v0.z + v1.z; acc.w += v0.w + v1.w;
    }
    if (j < e) {
        float4 v = ((const float4*)(d + (size_t)eo[j] * DD))[lane];
        acc.x += v.x; acc.y += v.y; acc.z += v.z; acc.w += v.w;
    }
    float inv = 1.0f / fmaxf((float)(e - s), 1.0f);
    acc.x *= inv; acc.y *= inv; acc.z *= inv; acc.w *= inv;
    ((float4*)(o + (size_t)node * DD))[lane] = acc;
}

// ---------------- bf16 m16n8k16 fused GEMM, double-buffered ----------------------
// Out[row] = act( In1[row] @ W1^T + In2[row] @ W2^T + bias ), rows gathered if GATHER.
// 3-term bf16 split (hh+lh+hl). 2-stage smem pipeline: phase p computes from stage
// p&1 while phase p+2's LDGs are in flight; one barrier per phase. No reg cap.
#define RSTR 20
static constexpr int STAGE_WORDS = 128 * RSTR;                         // per array
static constexpr int GEMM_SMEM = 1024 + 2 * 4 * STAGE_WORDS * 4;       // 82944

template<bool HAS2, bool GATHER, bool RELU, bool HASBIAS>
__global__ __launch_bounds__(512)
void gemm_tc(const float* __restrict__ In1, int in1Stride, long in1BStr,
             const float* __restrict__ W1, int w1Stride, long w1BStr,
             const float* __restrict__ In2, long in2BStr,
             const float* __restrict__ W2, int w2Stride, long w2BStr,
             const float* __restrict__ bias, long biasBStr,
             const int*   __restrict__ ridx,
             float* __restrict__ Out, long outBStr, int nrows) {
    extern __shared__ __align__(16) char smem[];
    int*      sRow  = (int*)smem;               // 128 ints
    float*    sBias = (float*)(smem + 512);     // 128 floats
    uint32_t* sBase = (uint32_t*)(smem + 1024);

    {
        long a = blockIdx.y;
        In1 += a * in1BStr; W1 += a * w1BStr;
        if (HAS2) { In2 += a * in2BStr; W2 += a * w2BStr; }
        if (HASBIAS) bias += a * biasBStr;
        Out += a * outBStr;
    }

    int tid = threadIdx.x, wid = tid >> 5, lane = tid & 31;
    int g = lane >> 2, tg = lane & 3;
    int warpM = wid >> 2, warpN = wid & 3;
    int row0 = blockIdx.x * 128;

    if (tid < 128) {
        int gr = row0 + tid;
        int e = 0;
        if (gr < nrows) e = GATHER ? ridx[gr] : gr;
        sRow[tid] = e;
        if (HASBIAS) sBias[tid] = bias[tid];
    }
    __syncthreads();

    float acc[2][4][4];
    #pragma unroll
    for (int mt = 0; mt < 2; mt++)
        #pragma unroll
        for (int nt = 0; nt < 4; nt++)
            #pragma unroll
            for (int i = 0; i < 4; i++) acc[mt][nt][i] = 0.0f;

    const int np = HAS2 ? 8 : 4;
    int frr = tid >> 2, fsg = (tid & 3) * 2;   // fill: row 0..127, seg pair base

    float4 rA[2], rB[2];

    auto ldg = [&](int p) {
        int op = HAS2 ? (p >> 2) : 0;
        int kc = (p & 3) * 32;
        #pragma unroll
        for (int q = 0; q < 2; q++) {
            int seg = fsg + q;
            const float* asrc;
            if (op == 0) asrc = In1 + (size_t)sRow[frr] * in1Stride + kc + seg * 4;
            else {
                int g2 = row0 + frr; if (g2 >= nrows) g2 = nrows - 1;
                asrc = In2 + (size_t)g2 * 128 + kc + seg * 4;
            }
            rA[q] = *(const float4*)asrc;
            const float* bw = (op == 0) ? W1 : W2;
            int bst = (op == 0) ? w1Stride : w2Stride;
            rB[q] = *(const float4*)(bw + (size_t)frr * bst + kc + seg * 4);
        }
    };
    auto sts = [&](int p) {
        uint32_t* st  = sBase + (p & 1) * (4 * STAGE_WORDS);
        uint32_t* tAh = st;
        uint32_t* tAl = st + STAGE_WORDS;
        uint32_t* tBh = st + 2 * STAGE_WORDS;
        uint32_t* tBl = st + 3 * STAGE_WORDS;
        #pragma unroll
        for (int q = 0; q < 2; q++) {
            int seg = fsg + q;
            int wa = frr * RSTR + seg * 2;
            uint32_t lo0, lo1;
            uint32_t hi0 = packsplit(rA[q].x, rA[q].y, lo0);
            uint32_t hi1 = packsplit(rA[q].z, rA[q].w, lo1);
            tAh[wa] = hi0; tAh[wa + 1] = hi1;
            tAl[wa] = lo0; tAl[wa + 1] = lo1;
            uint32_t wl0, wl1;
            uint32_t wh0 = packsplit(rB[q].x, rB[q].y, wl0);
            uint32_t wh1 = packsplit(rB[q].z, rB[q].w, wl1);
            tBh[wa] = wh0; tBh[wa + 1] = wh1;
            tBl[wa] = wl0; tBl[wa + 1] = wl1;
        }
    };

    // prologue
    ldg(0);
    sts(0);
    if (np > 1) ldg(1);
    __syncthreads();

    for (int p = 0; p < np; p++) {
        if (p + 1 < np) sts(p + 1);          // regs from ldg(p+1)
        if (p + 2 < np) ldg(p + 2);          // overlap DRAM latency with compute
        uint32_t* st  = sBase + (p & 1) * (4 * STAGE_WORDS);
        uint32_t* sAhi = st;
        uint32_t* sAlo = st + STAGE_WORDS;
        uint32_t* sBhi = st + 2 * STAGE_WORDS;
        uint32_t* sBlo = st + 3 * STAGE_WORDS;
        #pragma unroll
        for (int ks = 0; ks < 2; ks++) {
            int wb = ks * 8 + tg;
            uint32_t aH[2][4], aL[2][4];
            #pragma unroll
            for (int mt = 0; mt < 2; mt++) {
                int rb = (warpM * 32 + mt * 16 + g) * RSTR;
                aH[mt][0] = sAhi[rb + wb];
                aH[mt][1] = sAhi[rb + 8 * RSTR + wb];
                aH[mt][2] = sAhi[rb + wb + 4];
                aH[mt][3] = sAhi[rb + 8 * RSTR + wb + 4];
                aL[mt][0] = sAlo[rb + wb];
                aL[mt][1] = sAlo[rb + 8 * RSTR + wb];
                aL[mt][2] = sAlo[rb + wb + 4];
                aL[mt][3] = sAlo[rb + 8 * RSTR + wb + 4];
            }
            #pragma unroll
            for (int nt = 0; nt < 4; nt++) {
                int nb = (warpN * 32 + nt * 8 + g) * RSTR;
                uint32_t bh0 = sBhi[nb + wb], bh1 = sBhi[nb + wb + 4];
                uint32_t bl0 = sBlo[nb + wb], bl1 = sBlo[nb + wb + 4];
                #pragma unroll
                for (int mt = 0; mt < 2; mt++) {
                    mma16(acc[mt][nt], aH[mt], bh0, bh1);
                    mma16(acc[mt][nt], aL[mt], bh0, bh1);
                    mma16(acc[mt][nt], aH[mt], bl0, bl1);
                }
            }
        }
        __syncthreads();
    }

    // ---- epilogue ----
    #pragma unroll
    for (int mt = 0; mt < 2; mt++) {
        #pragma unroll
        for (int half = 0; half < 2; half++) {
            int lr = warpM * 32 + mt * 16 + g + half * 8;
            int grow = row0 + lr;
            if (grow < nrows) {
                int orow = GATHER ? sRow[lr] : grow;
                float* ob = Out + (size_t)orow * 128;
                #pragma unroll
                for (int nt = 0; nt < 4; nt++) {
                    int col = warpN * 32 + nt * 8 + tg * 2;
                    float v0 = acc[mt][nt][half * 2 + 0];
                    float v1 = acc[mt][nt][half * 2 + 1];
                    if (HASBIAS) { v0 += sBias[col]; v1 += sBias[col + 1]; }
                    if (RELU) { v0 = fmaxf(v0, 0.0f); v1 = fmaxf(v1, 0.0f); }
                    float2 pp; pp.x = v0; pp.y = v1;
                    *(float2*)(ob + col) = pp;
                }
            }
        }
    }
}

// ---------------- host orchestration -------------------------------------------
extern "C" void kernel_launch(void* const* d_in, const int* in_sizes, int n_in,
                              void* d_out, int out_size) {
    int iXI, iXA, iPF, iPOP, iEIA, iEIF, iPROJ, iAGGW, iAGGB,
        iWL1, iBL1, iWR1, iWL2, iBL2, iWR2, iWL3, iBL3, iWR3;
    if (in_sizes[3] == PP) {  // setup_inputs dict order
        iXI = 0; iXA = 1; iPF = 2; iPOP = 3; iEIA = 4; iEIF = 5;
        iPROJ = 6; iAGGW = 7; iAGGB = 8; iWL1 = 9; iBL1 = 10; iWR1 = 11;
        iWL2 = 12; iBL2 = 13; iWR2 = 14; iWL3 = 15; iBL3 = 16; iWR3 = 17;
    } else {                  // reference() signature order
        iXI = 0; iXA = 1; iPF = 2; iPROJ = 3; iAGGW = 4; iAGGB = 5;
        iWL1 = 6; iBL1 = 7; iWR1 = 8; iWL2 = 9; iBL2 = 10; iWR2 = 11;
        iWL3 = 12; iBL3 = 13; iWR3 = 14; iPOP = 15; iEIA = 16; iEIF = 17;
    }

    const float* xi   = (const float*)d_in[iXI];
    const float* xa   = (const float*)d_in[iXA];
    const float* pf   = (const float*)d_in[iPF];
    const int*   pop  = (const int*)d_in[iPOP];
    const int*   eia  = (const int*)d_in[iEIA];
    const int*   eif  = (const int*)d_in[iEIF];
    const float* proj = (const float*)d_in[iPROJ];
    const float* aggW = (const float*)d_in[iAGGW];
    const float* aggB = (const float*)d_in[iAGGB];
    const float* wl1  = (const float*)d_in[iWL1];
    const float* bl1  = (const float*)d_in[iBL1];
    const float* wr1  = (const float*)d_in[iWR1];
    const float* wl2  = (const float*)d_in[iWL2];
    const float* bl2  = (const float*)d_in[iBL2];
    const float* wr2  = (const float*)d_in[iWR2];
    const float* wl3  = (const float*)d_in[iWL3];
    const float* bl3  = (const float*)d_in[iBL3];
    const float* wr3  = (const float*)d_in[iWR3];

    float* out = (float*)d_out;  // [x_ind_out (N*D)] then [x_att_out (A*N*D)]

    float *xatt_a, *xatt_b, *agg, *esf, *projT, *MT;
    int *fillp;
    cudaGetSymbolAddress((void**)&xatt_a, g_xatt_a);
    cudaGetSymbolAddress((void**)&xatt_b, g_xatt_b);
    cudaGetSymbolAddress((void**)&agg,    g_agg);
    cudaGetSymbolAddress((void**)&esf,    g_esf);
    cudaGetSymbolAddress((void**)&projT,  g_projT);
    cudaGetSymbolAddress((void**)&MT,     g_MT);
    cudaGetSymbolAddress((void**)&fillp,  g_fill);
    float* agg3 = agg + 3 * ND;

    cudaFuncSetAttribute(inv_kernel, cudaFuncAttributeMaxDynamicSharedMemorySize, 131072);
    cudaFuncSetAttribute(gemm_tc<false, false, false, false>,
                         cudaFuncAttributeMaxDynamicSharedMemorySize, GEMM_SMEM);
    cudaFuncSetAttribute(gemm_tc<true, true, true, true>,
                         cudaFuncAttributeMaxDynamicSharedMemorySize, GEMM_SMEM);
    cudaFuncSetAttribute(gemm_tc<true, false, false, true>,
                         cudaFuncAttributeMaxDynamicSharedMemorySize, GEMM_SMEM);
    cudaFuncSetAttribute(gemm_tc<false, true, true, false>,
                         cudaFuncAttributeMaxDynamicSharedMemorySize, GEMM_SMEM);

    const int gP = (PP + 127) / 128;  // 391
    const int gN = (NN + 127) / 128;  // 782
    const int eB = (EE + 255) / 256;
    const int nB = (NN + 7) / 8;

    // --- prep: transposes + inverse (smem GJ) ---
    transpose_wt<<<AA, 256>>>(projT, proj);
    inv_kernel<<<AA, 1024, 131072>>>(proj);

    // --- CSR build for all 7 graphs ---
    cudaMemsetAsync(fillp, 0, (size_t)7 * NN * sizeof(int), 0);
    hist_k<<<dim3(eB, 7), 256>>>(eia, eif);
    scan_k<<<7, 1024>>>();
    fill_k<<<dim3(eB, 7), 256>>>(eia, eif);

    // 3) esf[a] = PF[:,a,:] @ proj[a]
    gemm_tc<false, false, false, false><<<dim3(gP, AA), 512, GEMM_SMEM>>>(
        pf, AA * DD, DD, projT, 128, 16384,
        nullptr, 0, nullptr, 0, 0, nullptr, 0, nullptr,
        esf, (long)PD, PP);

    // 4) x_att_a = copy(xa); population rows = relu([xa[pop], esf] @ aggW^T + b)
    cudaMemcpyAsync(xatt_a, xa, AND * sizeof(float), cudaMemcpyDeviceToDevice, 0);
    gemm_tc<true, true, true, true><<<dim3(gP, AA), 512, GEMM_SMEM>>>(
        xa, DD, (long)ND, aggW, 256, 0,
        esf, (long)PD, aggW + 128, 256, 0,
        aggB, 0, pop,
        xatt_a, (long)ND, PP);

    // 5+10) agg[a] = seg-mean of xi: graphs 0-2 (dst-seg) and 6 (family) together
    gather_mean<<<dim3(nB, 4), 256>>>(xi, 0, 0, 1, agg, (long)ND);

    // 6) x_att_b = agg @ W_l1^T + b_l1 + x_att_a @ W_r1^T
    gemm_tc<true, false, false, true><<<dim3(gN, AA), 512, GEMM_SMEM>>>(
        agg, DD, (long)ND, wl1, 128, 16384,
        xatt_a, (long)ND, wr1, 128, 16384,
        bl1, DD, nullptr,
        xatt_b, (long)ND, NN);

    // 7) population rows: x_att_b[pop] = relu(x_att_b[pop] @ (inv(proj)+I))
    gemm_tc<false, true, true, false><<<dim3(gP, AA), 512, GEMM_SMEM>>>(
        xatt_b, DD, (long)ND, MT, 128, 16384,
        nullptr, 0, nullptr, 0, 0, nullptr, 0, pop,
        xatt_b, (long)ND, PP);

    // 8) agg[a] = seg-mean of x_att_b over src (graphs 3-5)
    gather_mean<<<dim3(nB, AA), 256>>>(xatt_b, (long)ND, 3, 0, agg, (long)ND);

    // 9) x_att_out = agg @ W_l2^T + b_l2 + x_att_b @ W_r2^T  -> d_out[N*D:]
    gemm_tc<true, false, false, true><<<dim3(gN, AA), 512, GEMM_SMEM>>>(
        agg, DD, (long)ND, wl2, 128, 16384,
        xatt_b, (long)ND, wr2, 128, 16384,
        bl2, DD, nullptr,
        out + ND, (long)ND, NN);

    // 11) x_ind_out = agg3 @ W_l3^T + b_l3 + xi @ W_r3^T -> d_out[0:]
    gemm_tc<true, false, false, true><<<dim3(gN, 1), 512, GEMM_SMEM>>>(
        agg3, DD, 0, wl3, 128, 0,
        xi, 0, wr3, 128, 0,
        bl3, 0, nullptr,
        out, 0, NN);
}